// round 1
// baseline (speedup 1.0000x reference)
#include <cuda_runtime.h>

#define NN 50000
#define EE 800000
#define DD 128
#define BB 100
#define SLOPEV 0.01f

#define TILE_R 64
#define NTHR 256
#define XT_S 68   // padded smem row stride (floats), 16B-aligned

typedef unsigned long long ull;

// ---------------- scratch (device globals; no allocation allowed) ----------------
__device__ float g_h[NN * DD];
__device__ float g_u[NN * DD];
__device__ float g_A[NN * DD];    // h @ Weu[0:128]
__device__ float g_Bm[NN * DD];   // h @ Weu[128:256] + u @ Weu[384:512] + beu
__device__ float g_C[NN * DD];    // h @ Wnu[0:128] + u @ Wnu[256:384] + bnu
__device__ float g_hf[NN * DD];   // segment sum of f_new by dst (atomics)
__device__ float g_deg[NN];       // raw in-degree counts (float)
__device__ float g_nn[NN * DD];   // node_new
__device__ float g_gnew[BB * DD]; // graph update output

// ---------------- helpers ----------------
__device__ __forceinline__ float lrelu(float x) { return x > 0.f ? x : SLOPEV * x; }

__device__ __forceinline__ ull pack2(float x, float y) {
    ull r; asm("mov.b64 %0, {%1, %2};" : "=l"(r) : "f"(x), "f"(y)); return r;
}
__device__ __forceinline__ void unpack2(ull v, float& x, float& y) {
    asm("mov.b64 {%0, %1}, %2;" : "=f"(x), "=f"(y) : "l"(v));
}
__device__ __forceinline__ ull ffma2(ull a, ull b, ull c) {
    ull d; asm("fma.rn.f32x2 %0, %1, %2, %3;" : "=l"(d) : "l"(a), "l"(b), "l"(c)); return d;
}

struct Acc { ull v[4][4]; };

__device__ __forceinline__ void acc_zero(Acc& a) {
#pragma unroll
    for (int i = 0; i < 4; i++)
#pragma unroll
        for (int j = 0; j < 4; j++) a.v[i][j] = 0ull;
}

__device__ __forceinline__ void unpack_row(const Acc& acc, int i, float* z) {
#pragma unroll
    for (int j = 0; j < 4; j++) unpack2(acc.v[i][j], z[2 * j], z[2 * j + 1]);
}

// Load [64 x 128] tile of X (row-major, row stride DD) transposed into XT[k][r] (stride XT_S).
// Rows >= M are zero-filled. Optional per-row scale rs[r] (local row index).
template <bool SCALED>
__device__ __forceinline__ void load_tileT(const float* __restrict__ X, int rb, int M,
                                           float* __restrict__ XT, const float* __restrict__ rs) {
    int tid = threadIdx.x;
#pragma unroll
    for (int i = 0; i < 8; i++) {
        int idx = i * NTHR + tid;                 // 0..2047
        int r = (idx >> 2) & 63;
        int k4 = (idx & 3) | ((idx >> 8) << 2);   // 0..31
        float4 v = make_float4(0.f, 0.f, 0.f, 0.f);
        int gr = rb + r;
        if (gr < M) v = *(const float4*)(X + (size_t)gr * DD + k4 * 4);
        if (SCALED) { float s = rs[r]; v.x *= s; v.y *= s; v.z *= s; v.w *= s; }
        XT[(k4 * 4 + 0) * XT_S + r] = v.x;
        XT[(k4 * 4 + 1) * XT_S + r] = v.y;
        XT[(k4 * 4 + 2) * XT_S + r] = v.z;
        XT[(k4 * 4 + 3) * XT_S + r] = v.w;
    }
}

// acc += XT(64x128, transposed) @ W(128x128, row-major). Weights staged chunk-wise in Wsm[32*DD].
__device__ __forceinline__ void mm_pass(const float* __restrict__ XT, const float* __restrict__ W,
                                        float* __restrict__ Wsm, Acc& acc, int r0, int c0) {
    int tid = threadIdx.x;
    for (int kc = 0; kc < 4; ++kc) {
        __syncthreads();
#pragma unroll
        for (int i = 0; i < 4; ++i) {
            int idx = i * NTHR + tid;             // 0..1023 float4 slots
            int k = idx >> 5;
            int c4 = idx & 31;
            *(float4*)(Wsm + k * DD + c4 * 4) = *(const float4*)(W + (size_t)(kc * 32 + k) * DD + c4 * 4);
        }
        __syncthreads();
#pragma unroll
        for (int k = 0; k < 32; ++k) {
            float4 a4 = *(const float4*)(XT + (kc * 32 + k) * XT_S + r0);
            const float* wr = Wsm + k * DD + c0;
            ull bp[4];
            bp[0] = *(const ull*)(wr + 0);
            bp[1] = *(const ull*)(wr + 2);
            bp[2] = *(const ull*)(wr + 4);
            bp[3] = *(const ull*)(wr + 6);
            ull ap[4];
            ap[0] = pack2(a4.x, a4.x);
            ap[1] = pack2(a4.y, a4.y);
            ap[2] = pack2(a4.z, a4.z);
            ap[3] = pack2(a4.w, a4.w);
#pragma unroll
            for (int i = 0; i < 4; i++)
#pragma unroll
                for (int j = 0; j < 4; j++) acc.v[i][j] = ffma2(ap[i], bp[j], acc.v[i][j]);
        }
    }
}

__device__ __forceinline__ void store_tile(const Acc& acc, float* __restrict__ Y, int rb, int r0, int c0,
                                           const float* __restrict__ bias, bool do_act, int M) {
    float bb[8];
    if (bias) {
        float4 b0 = *(const float4*)(bias + c0);
        float4 b1 = *(const float4*)(bias + c0 + 4);
        bb[0] = b0.x; bb[1] = b0.y; bb[2] = b0.z; bb[3] = b0.w;
        bb[4] = b1.x; bb[5] = b1.y; bb[6] = b1.z; bb[7] = b1.w;
    } else {
#pragma unroll
        for (int j = 0; j < 8; j++) bb[j] = 0.f;
    }
#pragma unroll
    for (int i = 0; i < 4; i++) {
        int r = rb + r0 + i;
        if (r >= M) continue;
        float z[8];
        unpack_row(acc, i, z);
#pragma unroll
        for (int j = 0; j < 8; j++) { z[j] += bb[j]; if (do_act) z[j] = lrelu(z[j]); }
        *(float4*)(Y + (size_t)r * DD + c0) = make_float4(z[0], z[1], z[2], z[3]);
        *(float4*)(Y + (size_t)r * DD + c0 + 4) = make_float4(z[4], z[5], z[6], z[7]);
    }
}

// ---------------- kernels ----------------
__global__ void k_zero() {
    int idx = blockIdx.x * blockDim.x + threadIdx.x;
    int stride = gridDim.x * blockDim.x;
    float4 z = make_float4(0.f, 0.f, 0.f, 0.f);
    for (int i = idx; i < NN * DD / 4; i += stride) ((float4*)g_hf)[i] = z;
    for (int i = idx; i < NN; i += stride) g_deg[i] = 0.f;
}

// Y = act(X @ W + b); which==0 -> g_h, which==1 -> g_u
__global__ void __launch_bounds__(NTHR, 2) k_gemm_act(const float* __restrict__ X,
                                                      const float* __restrict__ W,
                                                      const float* __restrict__ bias,
                                                      int which, int M) {
    extern __shared__ float sm[];
    float* XT = sm;
    float* Wsm = sm + DD * XT_S;
    int tid = threadIdx.x, tx = tid & 15, ty = tid >> 4;
    int r0 = ty * 4, c0 = tx * 8;
    int rb = blockIdx.x * TILE_R;
    load_tileT<false>(X, rb, M, XT, nullptr);
    Acc acc; acc_zero(acc);
    mm_pass(XT, W, Wsm, acc, r0, c0);
    float* Y = which ? g_u : g_h;
    store_tile(acc, Y, rb, r0, c0, bias, true, M);
}

// A = h@Weu0 ; Bm = h@Weu1 + u@Weu3 + beu ; C = h@Wnu0 + u@Wnu2 + bnu
__global__ void __launch_bounds__(NTHR, 2) k_nodepre(const float* __restrict__ Weu,
                                                     const float* __restrict__ beu,
                                                     const float* __restrict__ Wnu,
                                                     const float* __restrict__ bnu) {
    extern __shared__ float sm[];
    float* hT = sm;
    float* uT = sm + DD * XT_S;
    float* Wsm = uT + DD * XT_S;
    int tid = threadIdx.x, tx = tid & 15, ty = tid >> 4;
    int r0 = ty * 4, c0 = tx * 8;
    int rb = blockIdx.x * TILE_R;
    load_tileT<false>(g_h, rb, NN, hT, nullptr);
    load_tileT<false>(g_u, rb, NN, uT, nullptr);
    Acc acc;
    acc_zero(acc);
    mm_pass(hT, Weu, Wsm, acc, r0, c0);
    store_tile(acc, g_A, rb, r0, c0, nullptr, false, NN);
    acc_zero(acc);
    mm_pass(hT, Weu + (size_t)128 * DD, Wsm, acc, r0, c0);
    mm_pass(uT, Weu + (size_t)384 * DD, Wsm, acc, r0, c0);
    store_tile(acc, g_Bm, rb, r0, c0, beu, false, NN);
    acc_zero(acc);
    mm_pass(hT, Wnu, Wsm, acc, r0, c0);
    mm_pass(uT, Wnu + (size_t)256 * DD, Wsm, acc, r0, c0);
    store_tile(acc, g_C, rb, r0, c0, bnu, false, NN);
}

// Per-edge: f = act(ef@We+be); f_new = act(f@Weu2 + A[src] + Bm[dst]); outputs + segment sums
__global__ void __launch_bounds__(NTHR, 2) k_edge(const float* __restrict__ ef,
                                                  const int* __restrict__ src,
                                                  const int* __restrict__ dst,
                                                  const float* __restrict__ We,
                                                  const float* __restrict__ be,
                                                  const float* __restrict__ Weu,
                                                  float* __restrict__ out_edge) {
    extern __shared__ float sm[];
    float* XT = sm;
    float* FT = sm + DD * XT_S;
    float* Wsm = FT + DD * XT_S;
    int* ssrc = (int*)(Wsm + 32 * DD);
    int* sdst = ssrc + TILE_R;
    int tid = threadIdx.x, tx = tid & 15, ty = tid >> 4;
    int r0 = ty * 4, c0 = tx * 8;
    int eb = blockIdx.x * TILE_R;

    load_tileT<false>(ef, eb, EE, XT, nullptr);
    if (tid < TILE_R) { ssrc[tid] = src[eb + tid]; sdst[tid] = dst[eb + tid]; }

    Acc acc; acc_zero(acc);
    mm_pass(XT, We, Wsm, acc, r0, c0);   // first internal sync covers loads above

    {   // f = act(acc + be) -> FT (transposed)
        float4 b0 = *(const float4*)(be + c0);
        float4 b1 = *(const float4*)(be + c0 + 4);
        float bb[8] = { b0.x, b0.y, b0.z, b0.w, b1.x, b1.y, b1.z, b1.w };
#pragma unroll
        for (int i = 0; i < 4; i++) {
            float z[8];
            unpack_row(acc, i, z);
            int r = r0 + i;
#pragma unroll
            for (int j = 0; j < 8; j++) FT[(c0 + j) * XT_S + r] = lrelu(z[j] + bb[j]);
        }
    }

    acc_zero(acc);
    mm_pass(FT, Weu + (size_t)256 * DD, Wsm, acc, r0, c0);  // sync inside covers FT writes

#pragma unroll
    for (int i = 0; i < 4; i++) {
        int r = r0 + i;
        int e = eb + r;
        int s = ssrc[r], d = sdst[r];
        float z[8];
        unpack_row(acc, i, z);
        const float4* pa = (const float4*)(g_A + (size_t)s * DD + c0);
        const float4* pb = (const float4*)(g_Bm + (size_t)d * DD + c0);
        float4 a0 = pa[0], a1 = pa[1];
        float4 m0 = pb[0], m1 = pb[1];
        float fn[8];
        fn[0] = lrelu(z[0] + a0.x + m0.x);
        fn[1] = lrelu(z[1] + a0.y + m0.y);
        fn[2] = lrelu(z[2] + a0.z + m0.z);
        fn[3] = lrelu(z[3] + a0.w + m0.w);
        fn[4] = lrelu(z[4] + a1.x + m1.x);
        fn[5] = lrelu(z[5] + a1.y + m1.y);
        fn[6] = lrelu(z[6] + a1.z + m1.z);
        fn[7] = lrelu(z[7] + a1.w + m1.w);
        float4 o0 = make_float4(fn[0] + XT[(c0 + 0) * XT_S + r], fn[1] + XT[(c0 + 1) * XT_S + r],
                                fn[2] + XT[(c0 + 2) * XT_S + r], fn[3] + XT[(c0 + 3) * XT_S + r]);
        float4 o1 = make_float4(fn[4] + XT[(c0 + 4) * XT_S + r], fn[5] + XT[(c0 + 5) * XT_S + r],
                                fn[6] + XT[(c0 + 6) * XT_S + r], fn[7] + XT[(c0 + 7) * XT_S + r]);
        *(float4*)(out_edge + (size_t)e * DD + c0) = o0;
        *(float4*)(out_edge + (size_t)e * DD + c0 + 4) = o1;
        float* hp = g_hf + (size_t)d * DD + c0;
#pragma unroll
        for (int j = 0; j < 8; j++) atomicAdd(hp + j, fn[j]);
        if (tx == 0) atomicAdd(&g_deg[d], 1.0f);
    }
}

// node_new = act(C + (hf_sum/max(deg,1)) @ Wnu1); out_node = node_new + node_feats
__global__ void __launch_bounds__(NTHR, 2) k_nodeupd(const float* __restrict__ Wnu,
                                                     const float* __restrict__ nf,
                                                     float* __restrict__ out_node) {
    extern __shared__ float sm[];
    float* hfT = sm;
    float* Wsm = sm + DD * XT_S;
    float* sdeg = Wsm + 32 * DD;
    int tid = threadIdx.x, tx = tid & 15, ty = tid >> 4;
    int r0 = ty * 4, c0 = tx * 8;
    int rb = blockIdx.x * TILE_R;
    if (tid < TILE_R) {
        int n = rb + tid;
        float dv = (n < NN) ? g_deg[n] : 1.f;
        sdeg[tid] = 1.f / fmaxf(dv, 1.f);
    }
    __syncthreads();
    load_tileT<true>(g_hf, rb, NN, hfT, sdeg);
    Acc acc; acc_zero(acc);
    mm_pass(hfT, Wnu + (size_t)128 * DD, Wsm, acc, r0, c0);
#pragma unroll
    for (int i = 0; i < 4; i++) {
        int r = rb + r0 + i;
        if (r >= NN) continue;
        float z[8];
        unpack_row(acc, i, z);
        const float4* pc = (const float4*)(g_C + (size_t)r * DD + c0);
        const float4* pn = (const float4*)(nf + (size_t)r * DD + c0);
        float4 c0v = pc[0], c1v = pc[1];
        float4 n0v = pn[0], n1v = pn[1];
        float nnv[8];
        nnv[0] = lrelu(z[0] + c0v.x); nnv[1] = lrelu(z[1] + c0v.y);
        nnv[2] = lrelu(z[2] + c0v.z); nnv[3] = lrelu(z[3] + c0v.w);
        nnv[4] = lrelu(z[4] + c1v.x); nnv[5] = lrelu(z[5] + c1v.y);
        nnv[6] = lrelu(z[6] + c1v.z); nnv[7] = lrelu(z[7] + c1v.w);
        *(float4*)(g_nn + (size_t)r * DD + c0) = make_float4(nnv[0], nnv[1], nnv[2], nnv[3]);
        *(float4*)(g_nn + (size_t)r * DD + c0 + 4) = make_float4(nnv[4], nnv[5], nnv[6], nnv[7]);
        *(float4*)(out_node + (size_t)r * DD + c0) =
            make_float4(nnv[0] + n0v.x, nnv[1] + n0v.y, nnv[2] + n0v.z, nnv[3] + n0v.w);
        *(float4*)(out_node + (size_t)r * DD + c0 + 4) =
            make_float4(nnv[4] + n1v.x, nnv[5] + n1v.y, nnv[6] + n1v.z, nnv[7] + n1v.w);
    }
}

// One block per graph: pools + graph update g_new
__global__ void k_pool(const int* __restrict__ n2g, const float* __restrict__ gf,
                       const float* __restrict__ Wnu, const float* __restrict__ bnu) {
    int g = blockIdx.x;
    int c = threadIdx.x;  // 128 threads
    int lo = 0, hi = NN;
    while (lo < hi) { int m = (lo + hi) >> 1; if (n2g[m] < g) lo = m + 1; else hi = m; }
    int s = lo;
    lo = s; hi = NN;
    while (lo < hi) { int m = (lo + hi) >> 1; if (n2g[m] < g + 1) lo = m + 1; else hi = m; }
    int e = lo;

    float sn = 0.f, se = 0.f, sg = 0.f;
    for (int n = s; n < e; ++n) {
        sn += g_nn[(size_t)n * DD + c];
        se += g_hf[(size_t)n * DD + c];
        sg += gf[(size_t)n * DD + c];
    }
    __shared__ float red[DD];
    float dls = 0.f;
    for (int n = s + c; n < e; n += DD) dls += g_deg[n];
    red[c] = dls;
    __syncthreads();
    for (int st = DD / 2; st > 0; st >>= 1) {
        if (c < st) red[c] += red[c + st];
        __syncthreads();
    }
    float degsum = red[0];
    float cnt = fmaxf((float)(e - s), 1.f);
    __shared__ float snp[DD], sep[DD], sgp[DD];
    snp[c] = sn / cnt;
    sep[c] = se / fmaxf(degsum, 1.f);
    sgp[c] = sg / cnt;
    __syncthreads();
    float z = bnu[c];
    for (int k = 0; k < DD; k++) {
        z += snp[k] * Wnu[(size_t)k * DD + c];
        z += sep[k] * Wnu[(size_t)(DD + k) * DD + c];
        z += sgp[k] * Wnu[(size_t)(2 * DD + k) * DD + c];
    }
    g_gnew[(size_t)g * DD + c] = lrelu(z);
}

__global__ void k_gout(const int* __restrict__ n2g, const float* __restrict__ gf,
                       float* __restrict__ out_graph) {
    int idx = blockIdx.x * blockDim.x + threadIdx.x;  // over NN*32 float4s
    if (idx >= NN * (DD / 4)) return;
    int n = idx >> 5;
    int c4 = idx & 31;
    int g = n2g[n];
    float4 a = *(const float4*)(g_gnew + (size_t)g * DD + c4 * 4);
    float4 b = *(const float4*)(gf + (size_t)n * DD + c4 * 4);
    *(float4*)(out_graph + (size_t)n * DD + c4 * 4) = make_float4(a.x + b.x, a.y + b.y, a.z + b.z, a.w + b.w);
}

// ---------------- launch ----------------
extern "C" void kernel_launch(void* const* d_in, const int* in_sizes, int n_in,
                              void* d_out, int out_size) {
    const float* node_feats  = (const float*)d_in[0];
    const float* edge_feats  = (const float*)d_in[1];
    const float* graph_feats = (const float*)d_in[2];
    const int*   src = (const int*)d_in[3];
    const int*   dst = (const int*)d_in[4];
    const int*   n2g = (const int*)d_in[5];
    const float* Wn  = (const float*)d_in[6];
    const float* bn  = (const float*)d_in[7];
    const float* We  = (const float*)d_in[8];
    const float* be  = (const float*)d_in[9];
    const float* Wg  = (const float*)d_in[10];
    const float* bg  = (const float*)d_in[11];
    const float* Weu = (const float*)d_in[12];
    const float* beu = (const float*)d_in[13];
    const float* Wnu = (const float*)d_in[14];
    const float* bnu = (const float*)d_in[15];

    float* out_node  = (float*)d_out;
    float* out_edge  = out_node + (size_t)NN * DD;
    float* out_graph = out_edge + (size_t)EE * DD;

    const int smem_g1   = (DD * XT_S + 32 * DD) * (int)sizeof(float);
    const int smem_pre  = (2 * DD * XT_S + 32 * DD) * (int)sizeof(float);
    const int smem_edge = (2 * DD * XT_S + 32 * DD) * (int)sizeof(float) + 2 * TILE_R * (int)sizeof(int);
    const int smem_upd  = (DD * XT_S + 32 * DD) * (int)sizeof(float) + TILE_R * (int)sizeof(float);

    cudaFuncSetAttribute(k_gemm_act, cudaFuncAttributeMaxDynamicSharedMemorySize, smem_g1);
    cudaFuncSetAttribute(k_nodepre,  cudaFuncAttributeMaxDynamicSharedMemorySize, smem_pre);
    cudaFuncSetAttribute(k_edge,     cudaFuncAttributeMaxDynamicSharedMemorySize, smem_edge);
    cudaFuncSetAttribute(k_nodeupd,  cudaFuncAttributeMaxDynamicSharedMemorySize, smem_upd);

    int nodeBlocks = (NN + TILE_R - 1) / TILE_R;  // 782
    int edgeBlocks = EE / TILE_R;                 // 12500

    k_zero<<<1024, NTHR>>>();
    k_gemm_act<<<nodeBlocks, NTHR, smem_g1>>>(node_feats, Wn, bn, 0, NN);
    k_gemm_act<<<nodeBlocks, NTHR, smem_g1>>>(graph_feats, Wg, bg, 1, NN);
    k_nodepre<<<nodeBlocks, NTHR, smem_pre>>>(Weu, beu, Wnu, bnu);
    k_edge<<<edgeBlocks, NTHR, smem_edge>>>(edge_feats, src, dst, We, be, Weu, out_edge);
    k_nodeupd<<<nodeBlocks, NTHR, smem_upd>>>(Wnu, node_feats, out_node);
    k_pool<<<BB, DD>>>(n2g, graph_feats, Wnu, bnu);
    k_gout<<<(NN * (DD / 4) + NTHR - 1) / NTHR, NTHR>>>(n2g, graph_feats, out_graph);
}

// round 2
// speedup vs baseline: 1.4777x; 1.4777x over previous
#include <cuda_runtime.h>

#define NN 50000
#define EE 800000
#define DD 128
#define BB 100
#define SLOPEV 0.01f

#define TILE_R 128
#define NTHR 256
#define RSR 132   // row stride (floats) for row-major smem tile, 16B aligned

typedef unsigned long long ull;

// ---------------- scratch ----------------
__device__ float g_h[NN * DD];
__device__ float g_u[NN * DD];
__device__ float g_A[NN * DD];    // h @ Weu[0:128]
__device__ float g_Bm[NN * DD];   // h @ Weu[128:256] + u @ Weu[384:512] + beu
__device__ float g_C[NN * DD];    // h @ Wnu[0:128] + u @ Wnu[256:384] + bnu
__device__ float g_hf[NN * DD];   // segment sum of f_new by dst
__device__ float g_deg[NN];
__device__ float g_nn[NN * DD];
__device__ float g_gnew[BB * DD];

// ---------------- helpers ----------------
__device__ __forceinline__ float lrelu(float x) { return x > 0.f ? x : SLOPEV * x; }
__device__ __forceinline__ ull pack2(float x, float y) {
    ull r; asm("mov.b64 %0, {%1, %2};" : "=l"(r) : "f"(x), "f"(y)); return r;
}
__device__ __forceinline__ void unpack2(ull v, float& x, float& y) {
    asm("mov.b64 {%0, %1}, %2;" : "=f"(x), "=f"(y) : "l"(v));
}
__device__ __forceinline__ ull ffma2(ull a, ull b, ull c) {
    ull d; asm("fma.rn.f32x2 %0, %1, %2, %3;" : "=l"(d) : "l"(a), "l"(b), "l"(c)); return d;
}

// accumulator: 8 rows x 4 column-pairs (8 cols)
struct AccRM { ull v[8][4]; };
__device__ __forceinline__ void acc_zero(AccRM& a) {
#pragma unroll
    for (int i = 0; i < 8; i++)
#pragma unroll
        for (int j = 0; j < 4; j++) a.v[i][j] = 0ull;
}
// extract row i: 8 floats (cols c0..c0+7)
__device__ __forceinline__ void acc_row(const AccRM& a, int i, float* z) {
#pragma unroll
    for (int j = 0; j < 4; j++) unpack2(a.v[i][j], z[2 * j], z[2 * j + 1]);
}

// load [128 x 128] tile of X row-major into F (stride RSR). rows >= M zero-filled.
template <bool SCALED>
__device__ __forceinline__ void load_tile_rm(const float* __restrict__ X, int rb, int M,
                                             float* __restrict__ F, const float* __restrict__ rs) {
    int tid = threadIdx.x;
#pragma unroll
    for (int i = 0; i < 16; i++) {
        int idx = i * NTHR + tid;         // 0..4095
        int r = idx >> 5;
        int c4 = idx & 31;
        float4 v = make_float4(0.f, 0.f, 0.f, 0.f);
        if (rb + r < M) v = *(const float4*)(X + (size_t)(rb + r) * DD + c4 * 4);
        if (SCALED) { float s = rs[r]; v.x *= s; v.y *= s; v.z *= s; v.w *= s; }
        *(float4*)(F + r * RSR + c4 * 4) = v;
    }
}

// acc += F(128x128 row-major, stride RSR) @ W(128x128 row-major global), staged via Wsm
__device__ __forceinline__ void mm_rm(const float* __restrict__ F, const float* __restrict__ W,
                                      float* __restrict__ Wsm, AccRM& acc, int r0, int c0) {
    int tid = threadIdx.x;
    for (int kc = 0; kc < 4; ++kc) {
        __syncthreads();
#pragma unroll
        for (int i = 0; i < 4; ++i) {
            int idx = i * NTHR + tid;              // 0..1023 float4 slots
            int kk = idx >> 5;
            int c4 = idx & 31;
            *(float4*)(Wsm + kk * DD + c4 * 4) = *(const float4*)(W + (size_t)(kc * 32 + kk) * DD + c4 * 4);
        }
        __syncthreads();
#pragma unroll 2
        for (int k4 = 0; k4 < 8; ++k4) {
            float4 a[8];
#pragma unroll
            for (int i = 0; i < 8; i++)
                a[i] = *(const float4*)(F + (r0 + i) * RSR + kc * 32 + k4 * 4);
#pragma unroll
            for (int kk = 0; kk < 4; ++kk) {
                const float* wr = Wsm + (k4 * 4 + kk) * DD + c0;
                ull b[4];
                b[0] = *(const ull*)(wr + 0);
                b[1] = *(const ull*)(wr + 2);
                b[2] = *(const ull*)(wr + 4);
                b[3] = *(const ull*)(wr + 6);
#pragma unroll
                for (int i = 0; i < 8; i++) {
                    float av = (kk == 0) ? a[i].x : (kk == 1) ? a[i].y : (kk == 2) ? a[i].z : a[i].w;
                    ull ad = pack2(av, av);
#pragma unroll
                    for (int j = 0; j < 4; j++) acc.v[i][j] = ffma2(ad, b[j], acc.v[i][j]);
                }
            }
        }
    }
}

__device__ __forceinline__ void store_tile(const AccRM& acc, float* __restrict__ Y, int rb, int r0, int c0,
                                           const float* __restrict__ bias, bool do_act, int M) {
    float bb[8];
    if (bias) {
        float4 b0 = *(const float4*)(bias + c0);
        float4 b1 = *(const float4*)(bias + c0 + 4);
        bb[0] = b0.x; bb[1] = b0.y; bb[2] = b0.z; bb[3] = b0.w;
        bb[4] = b1.x; bb[5] = b1.y; bb[6] = b1.z; bb[7] = b1.w;
    } else {
#pragma unroll
        for (int j = 0; j < 8; j++) bb[j] = 0.f;
    }
#pragma unroll
    for (int i = 0; i < 8; i++) {
        int r = rb + r0 + i;
        if (r >= M) continue;
        float z[8];
        acc_row(acc, i, z);
#pragma unroll
        for (int j = 0; j < 8; j++) { z[j] += bb[j]; if (do_act) z[j] = lrelu(z[j]); }
        *(float4*)(Y + (size_t)r * DD + c0) = make_float4(z[0], z[1], z[2], z[3]);
        *(float4*)(Y + (size_t)r * DD + c0 + 4) = make_float4(z[4], z[5], z[6], z[7]);
    }
}

// ---------------- kernels ----------------
__global__ void k_zero() {
    int idx = blockIdx.x * blockDim.x + threadIdx.x;
    int stride = gridDim.x * blockDim.x;
    float4 z = make_float4(0.f, 0.f, 0.f, 0.f);
    for (int i = idx; i < NN * DD / 4; i += stride) ((float4*)g_hf)[i] = z;
    for (int i = idx; i < NN; i += stride) g_deg[i] = 0.f;
}

// Y = act(X @ W + b)
__global__ void __launch_bounds__(NTHR, 2) k_gemm_act(const float* __restrict__ X,
                                                      const float* __restrict__ W,
                                                      const float* __restrict__ bias,
                                                      float* __restrict__ Y, int M) {
    extern __shared__ float sm[];
    float* F = sm;
    float* Wsm = sm + DD * RSR;
    int tid = threadIdx.x, tx = tid & 15, ty = tid >> 4;
    int r0 = ty * 8, c0 = tx * 8;
    int rb = blockIdx.x * TILE_R;
    load_tile_rm<false>(X, rb, M, F, nullptr);
    AccRM acc; acc_zero(acc);
    mm_rm(F, W, Wsm, acc, r0, c0);
    store_tile(acc, Y, rb, r0, c0, bias, true, M);
}

// A = h@Weu0 ; Bm = h@Weu1 + u@Weu3 + beu ; C = h@Wnu0 + u@Wnu2 + bnu
__global__ void __launch_bounds__(NTHR, 2) k_nodepre(const float* __restrict__ Weu,
                                                     const float* __restrict__ beu,
                                                     const float* __restrict__ Wnu,
                                                     const float* __restrict__ bnu) {
    extern __shared__ float sm[];
    float* F = sm;
    float* Wsm = sm + DD * RSR;
    int tid = threadIdx.x, tx = tid & 15, ty = tid >> 4;
    int r0 = ty * 8, c0 = tx * 8;
    int rb = blockIdx.x * TILE_R;
    AccRM acc;

    load_tile_rm<false>(g_h, rb, NN, F, nullptr);
    acc_zero(acc);
    mm_rm(F, Weu, Wsm, acc, r0, c0);                       // A = h@Weu0
    store_tile(acc, g_A, rb, r0, c0, nullptr, false, NN);

    acc_zero(acc);
    mm_rm(F, Weu + (size_t)128 * DD, Wsm, acc, r0, c0);    // Bm += h@Weu1
    __syncthreads();
    load_tile_rm<false>(g_u, rb, NN, F, nullptr);
    mm_rm(F, Weu + (size_t)384 * DD, Wsm, acc, r0, c0);    // Bm += u@Weu3
    store_tile(acc, g_Bm, rb, r0, c0, beu, false, NN);

    acc_zero(acc);
    mm_rm(F, Wnu + (size_t)256 * DD, Wsm, acc, r0, c0);    // C += u@Wnu2
    __syncthreads();
    load_tile_rm<false>(g_h, rb, NN, F, nullptr);
    mm_rm(F, Wnu, Wsm, acc, r0, c0);                       // C += h@Wnu0
    store_tile(acc, g_C, rb, r0, c0, bnu, false, NN);
}

// Per-edge: f = act(ef@We+be); f_new = act(f@Weu2 + A[src] + Bm[dst]); outputs + segment sums
__global__ void __launch_bounds__(NTHR, 2) k_edge(const float* __restrict__ ef,
                                                  const int* __restrict__ src,
                                                  const int* __restrict__ dst,
                                                  const float* __restrict__ We,
                                                  const float* __restrict__ be,
                                                  const float* __restrict__ Weu,
                                                  float* __restrict__ out_edge) {
    extern __shared__ float sm[];
    float* F = sm;
    float* Wsm = sm + DD * RSR;
    int* ssrc = (int*)(Wsm + 32 * DD);
    int* sdst = ssrc + TILE_R;
    int tid = threadIdx.x, tx = tid & 15, ty = tid >> 4;
    int r0 = ty * 8, c0 = tx * 8;
    int eb = blockIdx.x * TILE_R;

    load_tile_rm<false>(ef, eb, EE, F, nullptr);
    if (tid < TILE_R) { ssrc[tid] = src[eb + tid]; sdst[tid] = dst[eb + tid]; }

    AccRM acc; acc_zero(acc);
    mm_rm(F, We, Wsm, acc, r0, c0);       // leading sync covers tile load + src/dst

    __syncthreads();                      // all reads of F (ef) done before overwrite
    {   // f = act(acc + be) -> F (row-major, in place)
        float4 b0 = *(const float4*)(be + c0);
        float4 b1 = *(const float4*)(be + c0 + 4);
        float bb[8] = { b0.x, b0.y, b0.z, b0.w, b1.x, b1.y, b1.z, b1.w };
#pragma unroll
        for (int i = 0; i < 8; i++) {
            float z[8];
            acc_row(acc, i, z);
            int r = r0 + i;
#pragma unroll
            for (int j = 0; j < 8; j++) z[j] = lrelu(z[j] + bb[j]);
            *(float4*)(F + r * RSR + c0) = make_float4(z[0], z[1], z[2], z[3]);
            *(float4*)(F + r * RSR + c0 + 4) = make_float4(z[4], z[5], z[6], z[7]);
        }
    }

    acc_zero(acc);
    mm_rm(F, Weu + (size_t)256 * DD, Wsm, acc, r0, c0);   // leading sync covers f writes

#pragma unroll
    for (int i = 0; i < 8; i++) {
        int r = r0 + i;
        int e = eb + r;
        int s = ssrc[r], d = sdst[r];
        float z[8];
        acc_row(acc, i, z);
        const float4* pa = (const float4*)(g_A + (size_t)s * DD + c0);
        const float4* pb = (const float4*)(g_Bm + (size_t)d * DD + c0);
        const float4* pe = (const float4*)(ef + (size_t)e * DD + c0);
        float4 a0 = pa[0], a1 = pa[1];
        float4 m0 = pb[0], m1 = pb[1];
        float4 e0 = pe[0], e1 = pe[1];
        float fn[8];
        fn[0] = lrelu(z[0] + a0.x + m0.x);
        fn[1] = lrelu(z[1] + a0.y + m0.y);
        fn[2] = lrelu(z[2] + a0.z + m0.z);
        fn[3] = lrelu(z[3] + a0.w + m0.w);
        fn[4] = lrelu(z[4] + a1.x + m1.x);
        fn[5] = lrelu(z[5] + a1.y + m1.y);
        fn[6] = lrelu(z[6] + a1.z + m1.z);
        fn[7] = lrelu(z[7] + a1.w + m1.w);
        *(float4*)(out_edge + (size_t)e * DD + c0) = make_float4(fn[0] + e0.x, fn[1] + e0.y, fn[2] + e0.z, fn[3] + e0.w);
        *(float4*)(out_edge + (size_t)e * DD + c0 + 4) = make_float4(fn[4] + e1.x, fn[5] + e1.y, fn[6] + e1.z, fn[7] + e1.w);
        float* hp = g_hf + (size_t)d * DD + c0;
#pragma unroll
        for (int j = 0; j < 8; j++) atomicAdd(hp + j, fn[j]);
        if (tx == 0) atomicAdd(&g_deg[d], 1.0f);
    }
}

// node_new = act(C + (hf/max(deg,1)) @ Wnu1); out_node = node_new + node_feats
__global__ void __launch_bounds__(NTHR, 2) k_nodeupd(const float* __restrict__ Wnu,
                                                     const float* __restrict__ nf,
                                                     float* __restrict__ out_node) {
    extern __shared__ float sm[];
    float* F = sm;
    float* Wsm = sm + DD * RSR;
    float* sdeg = Wsm + 32 * DD;
    int tid = threadIdx.x, tx = tid & 15, ty = tid >> 4;
    int r0 = ty * 8, c0 = tx * 8;
    int rb = blockIdx.x * TILE_R;
    if (tid < TILE_R) {
        int n = rb + tid;
        float dv = (n < NN) ? g_deg[n] : 1.f;
        sdeg[tid] = 1.f / fmaxf(dv, 1.f);
    }
    __syncthreads();
    load_tile_rm<true>(g_hf, rb, NN, F, sdeg);
    AccRM acc; acc_zero(acc);
    mm_rm(F, Wnu + (size_t)128 * DD, Wsm, acc, r0, c0);
#pragma unroll
    for (int i = 0; i < 8; i++) {
        int r = rb + r0 + i;
        if (r >= NN) continue;
        float z[8];
        acc_row(acc, i, z);
        const float4* pc = (const float4*)(g_C + (size_t)r * DD + c0);
        const float4* pn = (const float4*)(nf + (size_t)r * DD + c0);
        float4 c0v = pc[0], c1v = pc[1];
        float4 n0v = pn[0], n1v = pn[1];
        float nnv[8];
        nnv[0] = lrelu(z[0] + c0v.x); nnv[1] = lrelu(z[1] + c0v.y);
        nnv[2] = lrelu(z[2] + c0v.z); nnv[3] = lrelu(z[3] + c0v.w);
        nnv[4] = lrelu(z[4] + c1v.x); nnv[5] = lrelu(z[5] + c1v.y);
        nnv[6] = lrelu(z[6] + c1v.z); nnv[7] = lrelu(z[7] + c1v.w);
        *(float4*)(g_nn + (size_t)r * DD + c0) = make_float4(nnv[0], nnv[1], nnv[2], nnv[3]);
        *(float4*)(g_nn + (size_t)r * DD + c0 + 4) = make_float4(nnv[4], nnv[5], nnv[6], nnv[7]);
        *(float4*)(out_node + (size_t)r * DD + c0) =
            make_float4(nnv[0] + n0v.x, nnv[1] + n0v.y, nnv[2] + n0v.z, nnv[3] + n0v.w);
        *(float4*)(out_node + (size_t)r * DD + c0 + 4) =
            make_float4(nnv[4] + n1v.x, nnv[5] + n1v.y, nnv[6] + n1v.z, nnv[7] + n1v.w);
    }
}

// One block per graph: pools + graph update
__global__ void k_pool(const int* __restrict__ n2g, const float* __restrict__ gf,
                       const float* __restrict__ Wnu, const float* __restrict__ bnu) {
    int g = blockIdx.x;
    int c = threadIdx.x;  // 128 threads
    int lo = 0, hi = NN;
    while (lo < hi) { int m = (lo + hi) >> 1; if (n2g[m] < g) lo = m + 1; else hi = m; }
    int s = lo;
    lo = s; hi = NN;
    while (lo < hi) { int m = (lo + hi) >> 1; if (n2g[m] < g + 1) lo = m + 1; else hi = m; }
    int e = lo;

    float sn = 0.f, se = 0.f, sg = 0.f;
    for (int n = s; n < e; ++n) {
        sn += g_nn[(size_t)n * DD + c];
        se += g_hf[(size_t)n * DD + c];
        sg += gf[(size_t)n * DD + c];
    }
    __shared__ float red[DD];
    float dls = 0.f;
    for (int n = s + c; n < e; n += DD) dls += g_deg[n];
    red[c] = dls;
    __syncthreads();
    for (int st = DD / 2; st > 0; st >>= 1) {
        if (c < st) red[c] += red[c + st];
        __syncthreads();
    }
    float degsum = red[0];
    float cnt = fmaxf((float)(e - s), 1.f);
    __shared__ float snp[DD], sep[DD], sgp[DD];
    snp[c] = sn / cnt;
    sep[c] = se / fmaxf(degsum, 1.f);
    sgp[c] = sg / cnt;
    __syncthreads();
    float z = bnu[c];
    for (int k = 0; k < DD; k++) {
        z += snp[k] * Wnu[(size_t)k * DD + c];
        z += sep[k] * Wnu[(size_t)(DD + k) * DD + c];
        z += sgp[k] * Wnu[(size_t)(2 * DD + k) * DD + c];
    }
    g_gnew[(size_t)g * DD + c] = lrelu(z);
}

__global__ void k_gout(const int* __restrict__ n2g, const float* __restrict__ gf,
                       float* __restrict__ out_graph) {
    int idx = blockIdx.x * blockDim.x + threadIdx.x;
    if (idx >= NN * (DD / 4)) return;
    int n = idx >> 5;
    int c4 = idx & 31;
    int g = n2g[n];
    float4 a = *(const float4*)(g_gnew + (size_t)g * DD + c4 * 4);
    float4 b = *(const float4*)(gf + (size_t)n * DD + c4 * 4);
    *(float4*)(out_graph + (size_t)n * DD + c4 * 4) = make_float4(a.x + b.x, a.y + b.y, a.z + b.z, a.w + b.w);
}

// ---------------- launch ----------------
extern "C" void kernel_launch(void* const* d_in, const int* in_sizes, int n_in,
                              void* d_out, int out_size) {
    const float* node_feats  = (const float*)d_in[0];
    const float* edge_feats  = (const float*)d_in[1];
    const float* graph_feats = (const float*)d_in[2];
    const int*   src = (const int*)d_in[3];
    const int*   dst = (const int*)d_in[4];
    const int*   n2g = (const int*)d_in[5];
    const float* Wn  = (const float*)d_in[6];
    const float* bn  = (const float*)d_in[7];
    const float* We  = (const float*)d_in[8];
    const float* be  = (const float*)d_in[9];
    const float* Wg  = (const float*)d_in[10];
    const float* bg  = (const float*)d_in[11];
    const float* Weu = (const float*)d_in[12];
    const float* beu = (const float*)d_in[13];
    const float* Wnu = (const float*)d_in[14];
    const float* bnu = (const float*)d_in[15];

    float* out_node  = (float*)d_out;
    float* out_edge  = out_node + (size_t)NN * DD;
    float* out_graph = out_edge + (size_t)EE * DD;

    const int base = (DD * RSR + 32 * DD) * (int)sizeof(float);   // 83968
    const int smem_g1   = base;
    const int smem_pre  = base;
    const int smem_edge = base + 2 * TILE_R * (int)sizeof(int);
    const int smem_upd  = base + TILE_R * (int)sizeof(float);

    cudaFuncSetAttribute(k_gemm_act, cudaFuncAttributeMaxDynamicSharedMemorySize, smem_g1);
    cudaFuncSetAttribute(k_nodepre,  cudaFuncAttributeMaxDynamicSharedMemorySize, smem_pre);
    cudaFuncSetAttribute(k_edge,     cudaFuncAttributeMaxDynamicSharedMemorySize, smem_edge);
    cudaFuncSetAttribute(k_nodeupd,  cudaFuncAttributeMaxDynamicSharedMemorySize, smem_upd);

    int nodeBlocks = (NN + TILE_R - 1) / TILE_R;  // 391
    int edgeBlocks = EE / TILE_R;                 // 6250

    float* d_gh; cudaGetSymbolAddress((void**)&d_gh, g_h);
    float* d_gu; cudaGetSymbolAddress((void**)&d_gu, g_u);

    k_zero<<<1024, NTHR>>>();
    k_gemm_act<<<nodeBlocks, NTHR, smem_g1>>>(node_feats, Wn, bn, d_gh, NN);
    k_gemm_act<<<nodeBlocks, NTHR, smem_g1>>>(graph_feats, Wg, bg, d_gu, NN);
    k_nodepre<<<nodeBlocks, NTHR, smem_pre>>>(Weu, beu, Wnu, bnu);
    k_edge<<<edgeBlocks, NTHR, smem_edge>>>(edge_feats, src, dst, We, be, Weu, out_edge);
    k_nodeupd<<<nodeBlocks, NTHR, smem_upd>>>(Wnu, node_feats, out_node);
    k_pool<<<BB, DD>>>(n2g, graph_feats, Wnu, bnu);
    k_gout<<<(NN * (DD / 4) + NTHR - 1) / NTHR, NTHR>>>(n2g, graph_feats, out_graph);
}

// round 3
// speedup vs baseline: 1.6574x; 1.1216x over previous
#include <cuda_runtime.h>

#define NN 50000
#define EE 800000
#define DD 128
#define BB 100
#define SLOPEV 0.01f

#define TILE_R 128
#define NTHR 256
#define RSR 132   // row stride (floats) for row-major smem tile, 16B aligned
#define WROWS 64  // W staging chunk rows

typedef unsigned long long ull;

// ---------------- scratch ----------------
__device__ float g_h[NN * DD];
__device__ float g_u[NN * DD];
__device__ float g_A[NN * DD];    // h @ Weu[0:128]
__device__ float g_Bm[NN * DD];   // h @ Weu[128:256] + u @ Weu[384:512] + beu
__device__ float g_C[NN * DD];    // h @ Wnu[0:128] + u @ Wnu[256:384] + bnu
__device__ float g_hf[NN * DD];   // segment sum of f_new by dst
__device__ float g_deg[NN];
__device__ float g_nn[NN * DD];
__device__ float g_gnew[BB * DD];

// ---------------- helpers ----------------
__device__ __forceinline__ float lrelu(float x) { return x > 0.f ? x : SLOPEV * x; }
__device__ __forceinline__ ull pack2(float x, float y) {
    ull r; asm("mov.b64 %0, {%1, %2};" : "=l"(r) : "f"(x), "f"(y)); return r;
}
__device__ __forceinline__ void unpack2(ull v, float& x, float& y) {
    asm("mov.b64 {%0, %1}, %2;" : "=f"(x), "=f"(y) : "l"(v));
}
__device__ __forceinline__ ull ffma2(ull a, ull b, ull c) {
    ull d; asm("fma.rn.f32x2 %0, %1, %2, %3;" : "=l"(d) : "l"(a), "l"(b), "l"(c)); return d;
}

// accumulator: 8 rows x 4 column-pairs (8 cols)
struct AccRM { ull v[8][4]; };
__device__ __forceinline__ void acc_zero(AccRM& a) {
#pragma unroll
    for (int i = 0; i < 8; i++)
#pragma unroll
        for (int j = 0; j < 4; j++) a.v[i][j] = 0ull;
}
__device__ __forceinline__ void acc_row(const AccRM& a, int i, float* z) {
#pragma unroll
    for (int j = 0; j < 4; j++) unpack2(a.v[i][j], z[2 * j], z[2 * j + 1]);
}

// load [128 x 128] tile of X row-major into F (stride RSR). rows >= M zero-filled.
template <bool SCALED>
__device__ __forceinline__ void load_tile_rm(const float* __restrict__ X, int rb, int M,
                                             float* __restrict__ F, const float* __restrict__ rs) {
    int tid = threadIdx.x;
#pragma unroll
    for (int i = 0; i < 16; i++) {
        int idx = i * NTHR + tid;         // 0..4095
        int r = idx >> 5;
        int c4 = idx & 31;
        float4 v = make_float4(0.f, 0.f, 0.f, 0.f);
        if (rb + r < M) v = *(const float4*)(X + (size_t)(rb + r) * DD + c4 * 4);
        if (SCALED) { float s = rs[r]; v.x *= s; v.y *= s; v.z *= s; v.w *= s; }
        *(float4*)(F + r * RSR + c4 * 4) = v;
    }
}

// acc += F(128x128 row-major, stride RSR) @ W(128x128 row-major global), staged 64 rows at a time
__device__ __forceinline__ void mm_rm(const float* __restrict__ F, const float* __restrict__ W,
                                      float* __restrict__ Wsm, AccRM& acc, int r0, int c0) {
    int tid = threadIdx.x;
#pragma unroll
    for (int kc = 0; kc < 2; ++kc) {
        __syncthreads();
#pragma unroll
        for (int i = 0; i < 8; ++i) {
            int idx = i * NTHR + tid;              // 0..2047 float4 slots
            int kk = idx >> 5;
            int c4 = idx & 31;
            *(float4*)(Wsm + kk * DD + c4 * 4) = *(const float4*)(W + (size_t)(kc * WROWS + kk) * DD + c4 * 4);
        }
        __syncthreads();
#pragma unroll 2
        for (int k4 = 0; k4 < 16; ++k4) {
            // hoist all loads of this iteration before the FMA block
            float4 a[8];
#pragma unroll
            for (int i = 0; i < 8; i++)
                a[i] = *(const float4*)(F + (r0 + i) * RSR + kc * WROWS + k4 * 4);
            float4 bl[4][2];
#pragma unroll
            for (int kk = 0; kk < 4; ++kk) {
                const float* wr = Wsm + (k4 * 4 + kk) * DD + c0;
                bl[kk][0] = *(const float4*)(wr);
                bl[kk][1] = *(const float4*)(wr + 4);
            }
#pragma unroll
            for (int kk = 0; kk < 4; ++kk) {
                ull b[4];
                b[0] = pack2(bl[kk][0].x, bl[kk][0].y);
                b[1] = pack2(bl[kk][0].z, bl[kk][0].w);
                b[2] = pack2(bl[kk][1].x, bl[kk][1].y);
                b[3] = pack2(bl[kk][1].z, bl[kk][1].w);
#pragma unroll
                for (int i = 0; i < 8; i++) {
                    float av = (kk == 0) ? a[i].x : (kk == 1) ? a[i].y : (kk == 2) ? a[i].z : a[i].w;
                    ull ad = pack2(av, av);
#pragma unroll
                    for (int j = 0; j < 4; j++) acc.v[i][j] = ffma2(ad, b[j], acc.v[i][j]);
                }
            }
        }
    }
}

__device__ __forceinline__ void store_tile(const AccRM& acc, float* __restrict__ Y, int rb, int r0, int c0,
                                           const float* __restrict__ bias, bool do_act, int M) {
    float bb[8];
    if (bias) {
        float4 b0 = *(const float4*)(bias + c0);
        float4 b1 = *(const float4*)(bias + c0 + 4);
        bb[0] = b0.x; bb[1] = b0.y; bb[2] = b0.z; bb[3] = b0.w;
        bb[4] = b1.x; bb[5] = b1.y; bb[6] = b1.z; bb[7] = b1.w;
    } else {
#pragma unroll
        for (int j = 0; j < 8; j++) bb[j] = 0.f;
    }
#pragma unroll
    for (int i = 0; i < 8; i++) {
        int r = rb + r0 + i;
        if (r >= M) continue;
        float z[8];
        acc_row(acc, i, z);
#pragma unroll
        for (int j = 0; j < 8; j++) { z[j] += bb[j]; if (do_act) z[j] = lrelu(z[j]); }
        *(float4*)(Y + (size_t)r * DD + c0) = make_float4(z[0], z[1], z[2], z[3]);
        *(float4*)(Y + (size_t)r * DD + c0 + 4) = make_float4(z[4], z[5], z[6], z[7]);
    }
}

// ---------------- kernels ----------------
__global__ void k_zero() {
    int idx = blockIdx.x * blockDim.x + threadIdx.x;
    int stride = gridDim.x * blockDim.x;
    float4 z = make_float4(0.f, 0.f, 0.f, 0.f);
    for (int i = idx; i < NN * DD / 4; i += stride) ((float4*)g_hf)[i] = z;
    for (int i = idx; i < NN; i += stride) g_deg[i] = 0.f;
}

// Y = act(X @ W + b)
__global__ void __launch_bounds__(NTHR, 2) k_gemm_act(const float* __restrict__ X,
                                                      const float* __restrict__ W,
                                                      const float* __restrict__ bias,
                                                      float* __restrict__ Y, int M) {
    extern __shared__ float sm[];
    float* F = sm;
    float* Wsm = sm + DD * RSR;
    int tid = threadIdx.x, tx = tid & 15, ty = tid >> 4;
    int r0 = ty * 8, c0 = tx * 8;
    int rb = blockIdx.x * TILE_R;
    load_tile_rm<false>(X, rb, M, F, nullptr);
    AccRM acc; acc_zero(acc);
    mm_rm(F, W, Wsm, acc, r0, c0);
    store_tile(acc, Y, rb, r0, c0, bias, true, M);
}

// A = h@Weu0 ; Bm = h@Weu1 + u@Weu3 + beu ; C = h@Wnu0 + u@Wnu2 + bnu
__global__ void __launch_bounds__(NTHR, 2) k_nodepre(const float* __restrict__ Weu,
                                                     const float* __restrict__ beu,
                                                     const float* __restrict__ Wnu,
                                                     const float* __restrict__ bnu) {
    extern __shared__ float sm[];
    float* F = sm;
    float* Wsm = sm + DD * RSR;
    int tid = threadIdx.x, tx = tid & 15, ty = tid >> 4;
    int r0 = ty * 8, c0 = tx * 8;
    int rb = blockIdx.x * TILE_R;
    AccRM acc;

    load_tile_rm<false>(g_h, rb, NN, F, nullptr);
    acc_zero(acc);
    mm_rm(F, Weu, Wsm, acc, r0, c0);                       // A = h@Weu0
    store_tile(acc, g_A, rb, r0, c0, nullptr, false, NN);

    acc_zero(acc);
    mm_rm(F, Weu + (size_t)128 * DD, Wsm, acc, r0, c0);    // Bm += h@Weu1
    __syncthreads();
    load_tile_rm<false>(g_u, rb, NN, F, nullptr);
    mm_rm(F, Weu + (size_t)384 * DD, Wsm, acc, r0, c0);    // Bm += u@Weu3
    store_tile(acc, g_Bm, rb, r0, c0, beu, false, NN);

    acc_zero(acc);
    mm_rm(F, Wnu + (size_t)256 * DD, Wsm, acc, r0, c0);    // C += u@Wnu2
    __syncthreads();
    load_tile_rm<false>(g_h, rb, NN, F, nullptr);
    mm_rm(F, Wnu, Wsm, acc, r0, c0);                       // C += h@Wnu0
    store_tile(acc, g_C, rb, r0, c0, bnu, false, NN);
}

// Per-edge: f = act(ef@We+be); f_new = act(f@Weu2 + A[src] + Bm[dst]); outputs + segment sums
__global__ void __launch_bounds__(NTHR, 2) k_edge(const float* __restrict__ ef,
                                                  const int* __restrict__ src,
                                                  const int* __restrict__ dst,
                                                  const float* __restrict__ We,
                                                  const float* __restrict__ be,
                                                  const float* __restrict__ Weu,
                                                  float* __restrict__ out_edge) {
    extern __shared__ float sm[];
    float* F = sm;
    float* Wsm = sm + DD * RSR;
    int* ssrc = (int*)(Wsm + WROWS * DD);
    int* sdst = ssrc + TILE_R;
    int tid = threadIdx.x, tx = tid & 15, ty = tid >> 4;
    int r0 = ty * 8, c0 = tx * 8;
    int eb = blockIdx.x * TILE_R;

    load_tile_rm<false>(ef, eb, EE, F, nullptr);
    if (tid < TILE_R) { ssrc[tid] = src[eb + tid]; sdst[tid] = dst[eb + tid]; }

    AccRM acc; acc_zero(acc);
    mm_rm(F, We, Wsm, acc, r0, c0);       // leading sync covers tile load + src/dst

    __syncthreads();                      // all reads of F (ef) done before overwrite
    {   // f = act(acc + be) -> F (row-major, in place)
        float4 b0 = *(const float4*)(be + c0);
        float4 b1 = *(const float4*)(be + c0 + 4);
        float bb[8] = { b0.x, b0.y, b0.z, b0.w, b1.x, b1.y, b1.z, b1.w };
#pragma unroll
        for (int i = 0; i < 8; i++) {
            float z[8];
            acc_row(acc, i, z);
            int r = r0 + i;
#pragma unroll
            for (int j = 0; j < 8; j++) z[j] = lrelu(z[j] + bb[j]);
            *(float4*)(F + r * RSR + c0) = make_float4(z[0], z[1], z[2], z[3]);
            *(float4*)(F + r * RSR + c0 + 4) = make_float4(z[4], z[5], z[6], z[7]);
        }
    }

    acc_zero(acc);
    mm_rm(F, Weu + (size_t)256 * DD, Wsm, acc, r0, c0);   // leading sync covers f writes

#pragma unroll
    for (int i = 0; i < 8; i++) {
        int r = r0 + i;
        int e = eb + r;
        int s = ssrc[r], d = sdst[r];
        float z[8];
        acc_row(acc, i, z);
        const float4* pa = (const float4*)(g_A + (size_t)s * DD + c0);
        const float4* pb = (const float4*)(g_Bm + (size_t)d * DD + c0);
        const float4* pe = (const float4*)(ef + (size_t)e * DD + c0);
        float4 a0 = pa[0], a1 = pa[1];
        float4 m0 = pb[0], m1 = pb[1];
        float4 e0 = pe[0], e1 = pe[1];
        float4 fn0, fn1;
        fn0.x = lrelu(z[0] + a0.x + m0.x);
        fn0.y = lrelu(z[1] + a0.y + m0.y);
        fn0.z = lrelu(z[2] + a0.z + m0.z);
        fn0.w = lrelu(z[3] + a0.w + m0.w);
        fn1.x = lrelu(z[4] + a1.x + m1.x);
        fn1.y = lrelu(z[5] + a1.y + m1.y);
        fn1.z = lrelu(z[6] + a1.z + m1.z);
        fn1.w = lrelu(z[7] + a1.w + m1.w);
        *(float4*)(out_edge + (size_t)e * DD + c0) = make_float4(fn0.x + e0.x, fn0.y + e0.y, fn0.z + e0.z, fn0.w + e0.w);
        *(float4*)(out_edge + (size_t)e * DD + c0 + 4) = make_float4(fn1.x + e1.x, fn1.y + e1.y, fn1.z + e1.z, fn1.w + e1.w);
        float4* hp = (float4*)(g_hf + (size_t)d * DD + c0);
        atomicAdd(hp, fn0);           // sm_90+ vector atomic (RED.128)
        atomicAdd(hp + 1, fn1);
        if (tx == 0) atomicAdd(&g_deg[d], 1.0f);
    }
}

// node_new = act(C + (hf/max(deg,1)) @ Wnu1); out_node = node_new + node_feats
__global__ void __launch_bounds__(NTHR, 2) k_nodeupd(const float* __restrict__ Wnu,
                                                     const float* __restrict__ nf,
                                                     float* __restrict__ out_node) {
    extern __shared__ float sm[];
    float* F = sm;
    float* Wsm = sm + DD * RSR;
    float* sdeg = Wsm + WROWS * DD;
    int tid = threadIdx.x, tx = tid & 15, ty = tid >> 4;
    int r0 = ty * 8, c0 = tx * 8;
    int rb = blockIdx.x * TILE_R;
    if (tid < TILE_R) {
        int n = rb + tid;
        float dv = (n < NN) ? g_deg[n] : 1.f;
        sdeg[tid] = 1.f / fmaxf(dv, 1.f);
    }
    __syncthreads();
    load_tile_rm<true>(g_hf, rb, NN, F, sdeg);
    AccRM acc; acc_zero(acc);
    mm_rm(F, Wnu + (size_t)128 * DD, Wsm, acc, r0, c0);
#pragma unroll
    for (int i = 0; i < 8; i++) {
        int r = rb + r0 + i;
        if (r >= NN) continue;
        float z[8];
        acc_row(acc, i, z);
        const float4* pc = (const float4*)(g_C + (size_t)r * DD + c0);
        const float4* pn = (const float4*)(nf + (size_t)r * DD + c0);
        float4 c0v = pc[0], c1v = pc[1];
        float4 n0v = pn[0], n1v = pn[1];
        float nnv[8];
        nnv[0] = lrelu(z[0] + c0v.x); nnv[1] = lrelu(z[1] + c0v.y);
        nnv[2] = lrelu(z[2] + c0v.z); nnv[3] = lrelu(z[3] + c0v.w);
        nnv[4] = lrelu(z[4] + c1v.x); nnv[5] = lrelu(z[5] + c1v.y);
        nnv[6] = lrelu(z[6] + c1v.z); nnv[7] = lrelu(z[7] + c1v.w);
        *(float4*)(g_nn + (size_t)r * DD + c0) = make_float4(nnv[0], nnv[1], nnv[2], nnv[3]);
        *(float4*)(g_nn + (size_t)r * DD + c0 + 4) = make_float4(nnv[4], nnv[5], nnv[6], nnv[7]);
        *(float4*)(out_node + (size_t)r * DD + c0) =
            make_float4(nnv[0] + n0v.x, nnv[1] + n0v.y, nnv[2] + n0v.z, nnv[3] + n0v.w);
        *(float4*)(out_node + (size_t)r * DD + c0 + 4) =
            make_float4(nnv[4] + n1v.x, nnv[5] + n1v.y, nnv[6] + n1v.z, nnv[7] + n1v.w);
    }
}

// One block per graph: pools + graph update
__global__ void k_pool(const int* __restrict__ n2g, const float* __restrict__ gf,
                       const float* __restrict__ Wnu, const float* __restrict__ bnu) {
    int g = blockIdx.x;
    int c = threadIdx.x;  // 128 threads
    int lo = 0, hi = NN;
    while (lo < hi) { int m = (lo + hi) >> 1; if (n2g[m] < g) lo = m + 1; else hi = m; }
    int s = lo;
    lo = s; hi = NN;
    while (lo < hi) { int m = (lo + hi) >> 1; if (n2g[m] < g + 1) lo = m + 1; else hi = m; }
    int e = lo;

    float sn = 0.f, se = 0.f, sg = 0.f;
    for (int n = s; n < e; ++n) {
        sn += g_nn[(size_t)n * DD + c];
        se += g_hf[(size_t)n * DD + c];
        sg += gf[(size_t)n * DD + c];
    }
    __shared__ float red[DD];
    float dls = 0.f;
    for (int n = s + c; n < e; n += DD) dls += g_deg[n];
    red[c] = dls;
    __syncthreads();
    for (int st = DD / 2; st > 0; st >>= 1) {
        if (c < st) red[c] += red[c + st];
        __syncthreads();
    }
    float degsum = red[0];
    float cnt = fmaxf((float)(e - s), 1.f);
    __shared__ float snp[DD], sep[DD], sgp[DD];
    snp[c] = sn / cnt;
    sep[c] = se / fmaxf(degsum, 1.f);
    sgp[c] = sg / cnt;
    __syncthreads();
    float z = bnu[c];
    for (int k = 0; k < DD; k++) {
        z += snp[k] * Wnu[(size_t)k * DD + c];
        z += sep[k] * Wnu[(size_t)(DD + k) * DD + c];
        z += sgp[k] * Wnu[(size_t)(2 * DD + k) * DD + c];
    }
    g_gnew[(size_t)g * DD + c] = lrelu(z);
}

__global__ void k_gout(const int* __restrict__ n2g, const float* __restrict__ gf,
                       float* __restrict__ out_graph) {
    int idx = blockIdx.x * blockDim.x + threadIdx.x;
    if (idx >= NN * (DD / 4)) return;
    int n = idx >> 5;
    int c4 = idx & 31;
    int g = n2g[n];
    float4 a = *(const float4*)(g_gnew + (size_t)g * DD + c4 * 4);
    float4 b = *(const float4*)(gf + (size_t)n * DD + c4 * 4);
    *(float4*)(out_graph + (size_t)n * DD + c4 * 4) = make_float4(a.x + b.x, a.y + b.y, a.z + b.z, a.w + b.w);
}

// ---------------- launch ----------------
extern "C" void kernel_launch(void* const* d_in, const int* in_sizes, int n_in,
                              void* d_out, int out_size) {
    const float* node_feats  = (const float*)d_in[0];
    const float* edge_feats  = (const float*)d_in[1];
    const float* graph_feats = (const float*)d_in[2];
    const int*   src = (const int*)d_in[3];
    const int*   dst = (const int*)d_in[4];
    const int*   n2g = (const int*)d_in[5];
    const float* Wn  = (const float*)d_in[6];
    const float* bn  = (const float*)d_in[7];
    const float* We  = (const float*)d_in[8];
    const float* be  = (const float*)d_in[9];
    const float* Wg  = (const float*)d_in[10];
    const float* bg  = (const float*)d_in[11];
    const float* Weu = (const float*)d_in[12];
    const float* beu = (const float*)d_in[13];
    const float* Wnu = (const float*)d_in[14];
    const float* bnu = (const float*)d_in[15];

    float* out_node  = (float*)d_out;
    float* out_edge  = out_node + (size_t)NN * DD;
    float* out_graph = out_edge + (size_t)EE * DD;

    const int base = (DD * RSR + WROWS * DD) * (int)sizeof(float);   // 100352
    const int smem_g1   = base;
    const int smem_pre  = base;
    const int smem_edge = base + 2 * TILE_R * (int)sizeof(int);
    const int smem_upd  = base + TILE_R * (int)sizeof(float);

    cudaFuncSetAttribute(k_gemm_act, cudaFuncAttributeMaxDynamicSharedMemorySize, smem_g1);
    cudaFuncSetAttribute(k_nodepre,  cudaFuncAttributeMaxDynamicSharedMemorySize, smem_pre);
    cudaFuncSetAttribute(k_edge,     cudaFuncAttributeMaxDynamicSharedMemorySize, smem_edge);
    cudaFuncSetAttribute(k_nodeupd,  cudaFuncAttributeMaxDynamicSharedMemorySize, smem_upd);

    int nodeBlocks = (NN + TILE_R - 1) / TILE_R;  // 391
    int edgeBlocks = EE / TILE_R;                 // 6250

    float* d_gh; cudaGetSymbolAddress((void**)&d_gh, g_h);
    float* d_gu; cudaGetSymbolAddress((void**)&d_gu, g_u);

    k_zero<<<1024, NTHR>>>();
    k_gemm_act<<<nodeBlocks, NTHR, smem_g1>>>(node_feats, Wn, bn, d_gh, NN);
    k_gemm_act<<<nodeBlocks, NTHR, smem_g1>>>(graph_feats, Wg, bg, d_gu, NN);
    k_nodepre<<<nodeBlocks, NTHR, smem_pre>>>(Weu, beu, Wnu, bnu);
    k_edge<<<edgeBlocks, NTHR, smem_edge>>>(edge_feats, src, dst, We, be, Weu, out_edge);
    k_nodeupd<<<nodeBlocks, NTHR, smem_upd>>>(Wnu, node_feats, out_node);
    k_pool<<<BB, DD>>>(n2g, graph_feats, Wnu, bnu);
    k_gout<<<(NN * (DD / 4) + NTHR - 1) / NTHR, NTHR>>>(n2g, graph_feats, out_graph);
}

// round 4
// speedup vs baseline: 1.6581x; 1.0004x over previous
#include <cuda_runtime.h>

#define NN 50000
#define EE 800000
#define DD 128
#define BB 100
#define SLOPEV 0.01f

#define TILE_R 128
#define NTHR 256
#define RSR 132   // row stride (floats) for row-major smem tile, 16B aligned
#define WROWS 64  // W staging chunk rows

typedef unsigned long long ull;

// ---------------- scratch ----------------
__device__ float g_h[NN * DD];
__device__ float g_u[NN * DD];
__device__ float g_A[NN * DD];    // h @ Weu[0:128]
__device__ float g_Bm[NN * DD];   // h @ Weu[128:256] + u @ Weu[384:512] + beu
__device__ float g_C[NN * DD];    // h @ Wnu[0:128] + u @ Wnu[256:384] + bnu
__device__ float g_hf[NN * DD];   // segment sum of f_new by dst
__device__ float g_deg[NN];
__device__ float g_nn[NN * DD];
__device__ float g_gnew[BB * DD];

// ---------------- helpers ----------------
__device__ __forceinline__ float lrelu(float x) { return x > 0.f ? x : SLOPEV * x; }
__device__ __forceinline__ ull pack2(float x, float y) {
    ull r; asm("mov.b64 %0, {%1, %2};" : "=l"(r) : "f"(x), "f"(y)); return r;
}
__device__ __forceinline__ void unpack2(ull v, float& x, float& y) {
    asm("mov.b64 {%0, %1}, %2;" : "=f"(x), "=f"(y) : "l"(v));
}
__device__ __forceinline__ ull ffma2(ull a, ull b, ull c) {
    ull d; asm("fma.rn.f32x2 %0, %1, %2, %3;" : "=l"(d) : "l"(a), "l"(b), "l"(c)); return d;
}

// accumulator: 8 rows x 4 column-pairs (8 cols)
struct AccRM { ull v[8][4]; };
__device__ __forceinline__ void acc_zero(AccRM& a) {
#pragma unroll
    for (int i = 0; i < 8; i++)
#pragma unroll
        for (int j = 0; j < 4; j++) a.v[i][j] = 0ull;
}
__device__ __forceinline__ void acc_row(const AccRM& a, int i, float* z) {
#pragma unroll
    for (int j = 0; j < 4; j++) unpack2(a.v[i][j], z[2 * j], z[2 * j + 1]);
}

// load [128 x 128] tile of X row-major into F (stride RSR). rows >= M zero-filled.
template <bool SCALED>
__device__ __forceinline__ void load_tile_rm(const float* __restrict__ X, int rb, int M,
                                             float* __restrict__ F, const float* __restrict__ rs) {
    int tid = threadIdx.x;
#pragma unroll
    for (int i = 0; i < 16; i++) {
        int idx = i * NTHR + tid;         // 0..4095
        int r = idx >> 5;
        int c4 = idx & 31;
        float4 v = make_float4(0.f, 0.f, 0.f, 0.f);
        if (rb + r < M) v = *(const float4*)(X + (size_t)(rb + r) * DD + c4 * 4);
        if (SCALED) { float s = rs[r]; v.x *= s; v.y *= s; v.z *= s; v.w *= s; }
        *(float4*)(F + r * RSR + c4 * 4) = v;
    }
}

// acc += F(128x128 row-major, stride RSR) @ W(128x128 row-major global), staged 64 rows at a time
__device__ __forceinline__ void mm_rm(const float* __restrict__ F, const float* __restrict__ W,
                                      float* __restrict__ Wsm, AccRM& acc, int r0, int c0) {
    int tid = threadIdx.x;
#pragma unroll
    for (int kc = 0; kc < 2; ++kc) {
        __syncthreads();
#pragma unroll
        for (int i = 0; i < 8; ++i) {
            int idx = i * NTHR + tid;              // 0..2047 float4 slots
            int kk = idx >> 5;
            int c4 = idx & 31;
            *(float4*)(Wsm + kk * DD + c4 * 4) = *(const float4*)(W + (size_t)(kc * WROWS + kk) * DD + c4 * 4);
        }
        __syncthreads();
#pragma unroll 2
        for (int k4 = 0; k4 < 16; ++k4) {
            // hoist all loads of this iteration before the FMA block
            float4 a[8];
#pragma unroll
            for (int i = 0; i < 8; i++)
                a[i] = *(const float4*)(F + (r0 + i) * RSR + kc * WROWS + k4 * 4);
            float4 bl[4][2];
#pragma unroll
            for (int kk = 0; kk < 4; ++kk) {
                const float* wr = Wsm + (k4 * 4 + kk) * DD + c0;
                bl[kk][0] = *(const float4*)(wr);
                bl[kk][1] = *(const float4*)(wr + 4);
            }
#pragma unroll
            for (int kk = 0; kk < 4; ++kk) {
                ull b[4];
                b[0] = pack2(bl[kk][0].x, bl[kk][0].y);
                b[1] = pack2(bl[kk][0].z, bl[kk][0].w);
                b[2] = pack2(bl[kk][1].x, bl[kk][1].y);
                b[3] = pack2(bl[kk][1].z, bl[kk][1].w);
#pragma unroll
                for (int i = 0; i < 8; i++) {
                    float av = (kk == 0) ? a[i].x : (kk == 1) ? a[i].y : (kk == 2) ? a[i].z : a[i].w;
                    ull ad = pack2(av, av);
#pragma unroll
                    for (int j = 0; j < 4; j++) acc.v[i][j] = ffma2(ad, b[j], acc.v[i][j]);
                }
            }
        }
    }
}

__device__ __forceinline__ void store_tile(const AccRM& acc, float* __restrict__ Y, int rb, int r0, int c0,
                                           const float* __restrict__ bias, bool do_act, int M) {
    float bb[8];
    if (bias) {
        float4 b0 = *(const float4*)(bias + c0);
        float4 b1 = *(const float4*)(bias + c0 + 4);
        bb[0] = b0.x; bb[1] = b0.y; bb[2] = b0.z; bb[3] = b0.w;
        bb[4] = b1.x; bb[5] = b1.y; bb[6] = b1.z; bb[7] = b1.w;
    } else {
#pragma unroll
        for (int j = 0; j < 8; j++) bb[j] = 0.f;
    }
#pragma unroll
    for (int i = 0; i < 8; i++) {
        int r = rb + r0 + i;
        if (r >= M) continue;
        float z[8];
        acc_row(acc, i, z);
#pragma unroll
        for (int j = 0; j < 8; j++) { z[j] += bb[j]; if (do_act) z[j] = lrelu(z[j]); }
        *(float4*)(Y + (size_t)r * DD + c0) = make_float4(z[0], z[1], z[2], z[3]);
        *(float4*)(Y + (size_t)r * DD + c0 + 4) = make_float4(z[4], z[5], z[6], z[7]);
    }
}

// ---------------- kernels ----------------
__global__ void k_zero() {
    int idx = blockIdx.x * blockDim.x + threadIdx.x;
    int stride = gridDim.x * blockDim.x;
    float4 z = make_float4(0.f, 0.f, 0.f, 0.f);
    for (int i = idx; i < NN * DD / 4; i += stride) ((float4*)g_hf)[i] = z;
    for (int i = idx; i < NN; i += stride) g_deg[i] = 0.f;
}

// Y = act(X @ W + b)
__global__ void __launch_bounds__(NTHR, 2) k_gemm_act(const float* __restrict__ X,
                                                      const float* __restrict__ W,
                                                      const float* __restrict__ bias,
                                                      float* __restrict__ Y, int M) {
    extern __shared__ float sm[];
    float* F = sm;
    float* Wsm = sm + DD * RSR;
    int tid = threadIdx.x, tx = tid & 15, ty = tid >> 4;
    int r0 = ty * 8, c0 = tx * 8;
    int rb = blockIdx.x * TILE_R;
    load_tile_rm<false>(X, rb, M, F, nullptr);
    AccRM acc; acc_zero(acc);
    mm_rm(F, W, Wsm, acc, r0, c0);
    store_tile(acc, Y, rb, r0, c0, bias, true, M);
}

// A = h@Weu0 ; Bm = h@Weu1 + u@Weu3 + beu ; C = h@Wnu0 + u@Wnu2 + bnu
__global__ void __launch_bounds__(NTHR, 2) k_nodepre(const float* __restrict__ Weu,
                                                     const float* __restrict__ beu,
                                                     const float* __restrict__ Wnu,
                                                     const float* __restrict__ bnu) {
    extern __shared__ float sm[];
    float* F = sm;
    float* Wsm = sm + DD * RSR;
    int tid = threadIdx.x, tx = tid & 15, ty = tid >> 4;
    int r0 = ty * 8, c0 = tx * 8;
    int rb = blockIdx.x * TILE_R;
    AccRM acc;

    load_tile_rm<false>(g_h, rb, NN, F, nullptr);
    acc_zero(acc);
    mm_rm(F, Weu, Wsm, acc, r0, c0);                       // A = h@Weu0
    store_tile(acc, g_A, rb, r0, c0, nullptr, false, NN);

    acc_zero(acc);
    mm_rm(F, Weu + (size_t)128 * DD, Wsm, acc, r0, c0);    // Bm += h@Weu1
    __syncthreads();
    load_tile_rm<false>(g_u, rb, NN, F, nullptr);
    mm_rm(F, Weu + (size_t)384 * DD, Wsm, acc, r0, c0);    // Bm += u@Weu3
    store_tile(acc, g_Bm, rb, r0, c0, beu, false, NN);

    acc_zero(acc);
    mm_rm(F, Wnu + (size_t)256 * DD, Wsm, acc, r0, c0);    // C += u@Wnu2
    __syncthreads();
    load_tile_rm<false>(g_h, rb, NN, F, nullptr);
    mm_rm(F, Wnu, Wsm, acc, r0, c0);                       // C += h@Wnu0
    store_tile(acc, g_C, rb, r0, c0, bnu, false, NN);
}

// Per-edge: f = act(ef@We+be); f_new = act(f@Weu2 + A[src] + Bm[dst]); outputs + segment sums
__global__ void __launch_bounds__(NTHR, 2) k_edge(const float* __restrict__ ef,
                                                  const int* __restrict__ src,
                                                  const int* __restrict__ dst,
                                                  const float* __restrict__ We,
                                                  const float* __restrict__ be,
                                                  const float* __restrict__ Weu,
                                                  float* __restrict__ out_edge) {
    extern __shared__ float sm[];
    float* F = sm;
    float* Wsm = sm + DD * RSR;
    int* ssrc = (int*)(Wsm + WROWS * DD);
    int* sdst = ssrc + TILE_R;
    int tid = threadIdx.x, tx = tid & 15, ty = tid >> 4;
    int r0 = ty * 8, c0 = tx * 8;
    int eb = blockIdx.x * TILE_R;

    load_tile_rm<false>(ef, eb, EE, F, nullptr);
    if (tid < TILE_R) { ssrc[tid] = src[eb + tid]; sdst[tid] = dst[eb + tid]; }

    AccRM acc; acc_zero(acc);
    mm_rm(F, We, Wsm, acc, r0, c0);       // leading sync covers tile load + src/dst

    __syncthreads();                      // all reads of F (ef) done before overwrite
    {   // f = act(acc + be) -> F (row-major, in place)
        float4 b0 = *(const float4*)(be + c0);
        float4 b1 = *(const float4*)(be + c0 + 4);
        float bb[8] = { b0.x, b0.y, b0.z, b0.w, b1.x, b1.y, b1.z, b1.w };
#pragma unroll
        for (int i = 0; i < 8; i++) {
            float z[8];
            acc_row(acc, i, z);
            int r = r0 + i;
#pragma unroll
            for (int j = 0; j < 8; j++) z[j] = lrelu(z[j] + bb[j]);
            *(float4*)(F + r * RSR + c0) = make_float4(z[0], z[1], z[2], z[3]);
            *(float4*)(F + r * RSR + c0 + 4) = make_float4(z[4], z[5], z[6], z[7]);
        }
    }

    acc_zero(acc);
    mm_rm(F, Weu + (size_t)256 * DD, Wsm, acc, r0, c0);   // leading sync covers f writes

#pragma unroll
    for (int i = 0; i < 8; i++) {
        int r = r0 + i;
        int e = eb + r;
        int s = ssrc[r], d = sdst[r];
        float z[8];
        acc_row(acc, i, z);
        const float4* pa = (const float4*)(g_A + (size_t)s * DD + c0);
        const float4* pb = (const float4*)(g_Bm + (size_t)d * DD + c0);
        const float4* pe = (const float4*)(ef + (size_t)e * DD + c0);
        float4 a0 = pa[0], a1 = pa[1];
        float4 m0 = pb[0], m1 = pb[1];
        float4 e0 = pe[0], e1 = pe[1];
        float4 fn0, fn1;
        fn0.x = lrelu(z[0] + a0.x + m0.x);
        fn0.y = lrelu(z[1] + a0.y + m0.y);
        fn0.z = lrelu(z[2] + a0.z + m0.z);
        fn0.w = lrelu(z[3] + a0.w + m0.w);
        fn1.x = lrelu(z[4] + a1.x + m1.x);
        fn1.y = lrelu(z[5] + a1.y + m1.y);
        fn1.z = lrelu(z[6] + a1.z + m1.z);
        fn1.w = lrelu(z[7] + a1.w + m1.w);
        *(float4*)(out_edge + (size_t)e * DD + c0) = make_float4(fn0.x + e0.x, fn0.y + e0.y, fn0.z + e0.z, fn0.w + e0.w);
        *(float4*)(out_edge + (size_t)e * DD + c0 + 4) = make_float4(fn1.x + e1.x, fn1.y + e1.y, fn1.z + e1.z, fn1.w + e1.w);
        float4* hp = (float4*)(g_hf + (size_t)d * DD + c0);
        atomicAdd(hp, fn0);           // sm_90+ vector atomic (RED.128)
        atomicAdd(hp + 1, fn1);
        if (tx == 0) atomicAdd(&g_deg[d], 1.0f);
    }
}

// node_new = act(C + (hf/max(deg,1)) @ Wnu1); out_node = node_new + node_feats
__global__ void __launch_bounds__(NTHR, 2) k_nodeupd(const float* __restrict__ Wnu,
                                                     const float* __restrict__ nf,
                                                     float* __restrict__ out_node) {
    extern __shared__ float sm[];
    float* F = sm;
    float* Wsm = sm + DD * RSR;
    float* sdeg = Wsm + WROWS * DD;
    int tid = threadIdx.x, tx = tid & 15, ty = tid >> 4;
    int r0 = ty * 8, c0 = tx * 8;
    int rb = blockIdx.x * TILE_R;
    if (tid < TILE_R) {
        int n = rb + tid;
        float dv = (n < NN) ? g_deg[n] : 1.f;
        sdeg[tid] = 1.f / fmaxf(dv, 1.f);
    }
    __syncthreads();
    load_tile_rm<true>(g_hf, rb, NN, F, sdeg);
    AccRM acc; acc_zero(acc);
    mm_rm(F, Wnu + (size_t)128 * DD, Wsm, acc, r0, c0);
#pragma unroll
    for (int i = 0; i < 8; i++) {
        int r = rb + r0 + i;
        if (r >= NN) continue;
        float z[8];
        acc_row(acc, i, z);
        const float4* pc = (const float4*)(g_C + (size_t)r * DD + c0);
        const float4* pn = (const float4*)(nf + (size_t)r * DD + c0);
        float4 c0v = pc[0], c1v = pc[1];
        float4 n0v = pn[0], n1v = pn[1];
        float nnv[8];
        nnv[0] = lrelu(z[0] + c0v.x); nnv[1] = lrelu(z[1] + c0v.y);
        nnv[2] = lrelu(z[2] + c0v.z); nnv[3] = lrelu(z[3] + c0v.w);
        nnv[4] = lrelu(z[4] + c1v.x); nnv[5] = lrelu(z[5] + c1v.y);
        nnv[6] = lrelu(z[6] + c1v.z); nnv[7] = lrelu(z[7] + c1v.w);
        *(float4*)(g_nn + (size_t)r * DD + c0) = make_float4(nnv[0], nnv[1], nnv[2], nnv[3]);
        *(float4*)(g_nn + (size_t)r * DD + c0 + 4) = make_float4(nnv[4], nnv[5], nnv[6], nnv[7]);
        *(float4*)(out_node + (size_t)r * DD + c0) =
            make_float4(nnv[0] + n0v.x, nnv[1] + n0v.y, nnv[2] + n0v.z, nnv[3] + n0v.w);
        *(float4*)(out_node + (size_t)r * DD + c0 + 4) =
            make_float4(nnv[4] + n1v.x, nnv[5] + n1v.y, nnv[6] + n1v.z, nnv[7] + n1v.w);
    }
}

// One block per graph: pools + graph update
__global__ void k_pool(const int* __restrict__ n2g, const float* __restrict__ gf,
                       const float* __restrict__ Wnu, const float* __restrict__ bnu) {
    int g = blockIdx.x;
    int c = threadIdx.x;  // 128 threads
    int lo = 0, hi = NN;
    while (lo < hi) { int m = (lo + hi) >> 1; if (n2g[m] < g) lo = m + 1; else hi = m; }
    int s = lo;
    lo = s; hi = NN;
    while (lo < hi) { int m = (lo + hi) >> 1; if (n2g[m] < g + 1) lo = m + 1; else hi = m; }
    int e = lo;

    float sn = 0.f, se = 0.f, sg = 0.f;
    for (int n = s; n < e; ++n) {
        sn += g_nn[(size_t)n * DD + c];
        se += g_hf[(size_t)n * DD + c];
        sg += gf[(size_t)n * DD + c];
    }
    __shared__ float red[DD];
    float dls = 0.f;
    for (int n = s + c; n < e; n += DD) dls += g_deg[n];
    red[c] = dls;
    __syncthreads();
    for (int st = DD / 2; st > 0; st >>= 1) {
        if (c < st) red[c] += red[c + st];
        __syncthreads();
    }
    float degsum = red[0];
    float cnt = fmaxf((float)(e - s), 1.f);
    __shared__ float snp[DD], sep[DD], sgp[DD];
    snp[c] = sn / cnt;
    sep[c] = se / fmaxf(degsum, 1.f);
    sgp[c] = sg / cnt;
    __syncthreads();
    float z = bnu[c];
    for (int k = 0; k < DD; k++) {
        z += snp[k] * Wnu[(size_t)k * DD + c];
        z += sep[k] * Wnu[(size_t)(DD + k) * DD + c];
        z += sgp[k] * Wnu[(size_t)(2 * DD + k) * DD + c];
    }
    g_gnew[(size_t)g * DD + c] = lrelu(z);
}

__global__ void k_gout(const int* __restrict__ n2g, const float* __restrict__ gf,
                       float* __restrict__ out_graph) {
    int idx = blockIdx.x * blockDim.x + threadIdx.x;
    if (idx >= NN * (DD / 4)) return;
    int n = idx >> 5;
    int c4 = idx & 31;
    int g = n2g[n];
    float4 a = *(const float4*)(g_gnew + (size_t)g * DD + c4 * 4);
    float4 b = *(const float4*)(gf + (size_t)n * DD + c4 * 4);
    *(float4*)(out_graph + (size_t)n * DD + c4 * 4) = make_float4(a.x + b.x, a.y + b.y, a.z + b.z, a.w + b.w);
}

// ---------------- launch ----------------
extern "C" void kernel_launch(void* const* d_in, const int* in_sizes, int n_in,
                              void* d_out, int out_size) {
    const float* node_feats  = (const float*)d_in[0];
    const float* edge_feats  = (const float*)d_in[1];
    const float* graph_feats = (const float*)d_in[2];
    const int*   src = (const int*)d_in[3];
    const int*   dst = (const int*)d_in[4];
    const int*   n2g = (const int*)d_in[5];
    const float* Wn  = (const float*)d_in[6];
    const float* bn  = (const float*)d_in[7];
    const float* We  = (const float*)d_in[8];
    const float* be  = (const float*)d_in[9];
    const float* Wg  = (const float*)d_in[10];
    const float* bg  = (const float*)d_in[11];
    const float* Weu = (const float*)d_in[12];
    const float* beu = (const float*)d_in[13];
    const float* Wnu = (const float*)d_in[14];
    const float* bnu = (const float*)d_in[15];

    float* out_node  = (float*)d_out;
    float* out_edge  = out_node + (size_t)NN * DD;
    float* out_graph = out_edge + (size_t)EE * DD;

    const int base = (DD * RSR + WROWS * DD) * (int)sizeof(float);   // 100352
    const int smem_g1   = base;
    const int smem_pre  = base;
    const int smem_edge = base + 2 * TILE_R * (int)sizeof(int);
    const int smem_upd  = base + TILE_R * (int)sizeof(float);

    cudaFuncSetAttribute(k_gemm_act, cudaFuncAttributeMaxDynamicSharedMemorySize, smem_g1);
    cudaFuncSetAttribute(k_nodepre,  cudaFuncAttributeMaxDynamicSharedMemorySize, smem_pre);
    cudaFuncSetAttribute(k_edge,     cudaFuncAttributeMaxDynamicSharedMemorySize, smem_edge);
    cudaFuncSetAttribute(k_nodeupd,  cudaFuncAttributeMaxDynamicSharedMemorySize, smem_upd);

    int nodeBlocks = (NN + TILE_R - 1) / TILE_R;  // 391
    int edgeBlocks = EE / TILE_R;                 // 6250

    float* d_gh; cudaGetSymbolAddress((void**)&d_gh, g_h);
    float* d_gu; cudaGetSymbolAddress((void**)&d_gu, g_u);

    k_zero<<<1024, NTHR>>>();
    k_gemm_act<<<nodeBlocks, NTHR, smem_g1>>>(node_feats, Wn, bn, d_gh, NN);
    k_gemm_act<<<nodeBlocks, NTHR, smem_g1>>>(graph_feats, Wg, bg, d_gu, NN);
    k_nodepre<<<nodeBlocks, NTHR, smem_pre>>>(Weu, beu, Wnu, bnu);
    k_edge<<<edgeBlocks, NTHR, smem_edge>>>(edge_feats, src, dst, We, be, Weu, out_edge);
    k_nodeupd<<<nodeBlocks, NTHR, smem_upd>>>(Wnu, node_feats, out_node);
    k_pool<<<BB, DD>>>(n2g, graph_feats, Wnu, bnu);
    k_gout<<<(NN * (DD / 4) + NTHR - 1) / NTHR, NTHR>>>(n2g, graph_feats, out_graph);
}

// round 8
// speedup vs baseline: 1.9002x; 1.1460x over previous
#include <cuda_runtime.h>
#include <cuda_bf16.h>
#include <cstdint>

#define NN 50000
#define EE 800000
#define DD 128
#define BB 100
#define SLOPEV 0.01f

#define TILE_R 128
#define NTHR 256
#define RSR 132
#define WROWS 64

typedef unsigned long long ull;

// ---------------- scratch ----------------
__device__ float g_h[NN * DD];
__device__ float g_u[NN * DD];
__device__ float g_A[NN * DD];    // h @ Weu[0:128]
__device__ float g_Bm[NN * DD];   // h @ Weu[128:256] + u @ Weu[384:512] + beu
__device__ float g_C[NN * DD];    // h @ Wnu[0:128] + u @ Wnu[256:384] + bnu
__device__ float g_hf[NN * DD];
__device__ float g_deg[NN];
__device__ float g_nn[NN * DD];
__device__ float g_gnew[BB * DD];
// prepped B operands: [N=128][K=128] bf16 pairs, XOR-swizzled word layout, hi/lo split
__device__ uint32_t g_We_h[8192];
__device__ uint32_t g_We_l[8192];
__device__ uint32_t g_Wu_h[8192];
__device__ uint32_t g_Wu_l[8192];

// ---------------- generic helpers ----------------
__device__ __forceinline__ float lrelu(float x) { return x > 0.f ? x : SLOPEV * x; }
__device__ __forceinline__ ull pack2(float x, float y) {
    ull r; asm("mov.b64 %0, {%1, %2};" : "=l"(r) : "f"(x), "f"(y)); return r;
}
__device__ __forceinline__ void unpack2(ull v, float& x, float& y) {
    asm("mov.b64 {%0, %1}, %2;" : "=f"(x), "=f"(y) : "l"(v));
}
__device__ __forceinline__ ull ffma2(ull a, ull b, ull c) {
    ull d; asm("fma.rn.f32x2 %0, %1, %2, %3;" : "=l"(d) : "l"(a), "l"(b), "l"(c)); return d;
}
// fp32 pair -> bf16x2 hi + bf16x2 lo residual
__device__ __forceinline__ void split2(float a, float b, uint32_t& hi, uint32_t& lo) {
    __nv_bfloat162 h = __floats2bfloat162_rn(a, b);
    float ra = a - __bfloat162float(h.x);
    float rb = b - __bfloat162float(h.y);
    __nv_bfloat162 l = __floats2bfloat162_rn(ra, rb);
    hi = *(uint32_t*)&h;
    lo = *(uint32_t*)&l;
}
// XOR-swizzled word index for a [128 rows][64 words] bf16-pair tile
__device__ __forceinline__ uint32_t aswz(int r, int wc) {
    return (uint32_t)(r * 64 + (wc ^ ((r & 7) << 2)));
}
// HMMA m16n8k16 bf16: D/C fp32
__device__ __forceinline__ void mma_bf16(float* c, uint32_t a0, uint32_t a1, uint32_t a2, uint32_t a3,
                                         uint32_t b0, uint32_t b1) {
    asm volatile(
        "mma.sync.aligned.m16n8k16.row.col.f32.bf16.bf16.f32 "
        "{%0,%1,%2,%3}, {%4,%5,%6,%7}, {%8,%9}, {%0,%1,%2,%3};"
        : "+f"(c[0]), "+f"(c[1]), "+f"(c[2]), "+f"(c[3])
        : "r"(a0), "r"(a1), "r"(a2), "r"(a3), "r"(b0), "r"(b1));
}

// ---------------- FFMA2 GEMM machinery (node-side kernels) ----------------
struct AccRM { ull v[8][4]; };
__device__ __forceinline__ void acc_zero(AccRM& a) {
#pragma unroll
    for (int i = 0; i < 8; i++)
#pragma unroll
        for (int j = 0; j < 4; j++) a.v[i][j] = 0ull;
}
__device__ __forceinline__ void acc_row(const AccRM& a, int i, float* z) {
#pragma unroll
    for (int j = 0; j < 4; j++) unpack2(a.v[i][j], z[2 * j], z[2 * j + 1]);
}

template <bool SCALED>
__device__ __forceinline__ void load_tile_rm(const float* __restrict__ X, int rb, int M,
                                             float* __restrict__ F, const float* __restrict__ rs) {
    int tid = threadIdx.x;
#pragma unroll
    for (int i = 0; i < 16; i++) {
        int idx = i * NTHR + tid;
        int r = idx >> 5;
        int c4 = idx & 31;
        float4 v = make_float4(0.f, 0.f, 0.f, 0.f);
        if (rb + r < M) v = *(const float4*)(X + (size_t)(rb + r) * DD + c4 * 4);
        if (SCALED) { float s = rs[r]; v.x *= s; v.y *= s; v.z *= s; v.w *= s; }
        *(float4*)(F + r * RSR + c4 * 4) = v;
    }
}

__device__ __forceinline__ void mm_rm(const float* __restrict__ F, const float* __restrict__ W,
                                      float* __restrict__ Wsm, AccRM& acc, int r0, int c0) {
    int tid = threadIdx.x;
#pragma unroll
    for (int kc = 0; kc < 2; ++kc) {
        __syncthreads();
#pragma unroll
        for (int i = 0; i < 8; ++i) {
            int idx = i * NTHR + tid;
            int kk = idx >> 5;
            int c4 = idx & 31;
            *(float4*)(Wsm + kk * DD + c4 * 4) = *(const float4*)(W + (size_t)(kc * WROWS + kk) * DD + c4 * 4);
        }
        __syncthreads();
#pragma unroll 2
        for (int k4 = 0; k4 < 16; ++k4) {
            float4 a[8];
#pragma unroll
            for (int i = 0; i < 8; i++)
                a[i] = *(const float4*)(F + (r0 + i) * RSR + kc * WROWS + k4 * 4);
            float4 bl[4][2];
#pragma unroll
            for (int kk = 0; kk < 4; ++kk) {
                const float* wr = Wsm + (k4 * 4 + kk) * DD + c0;
                bl[kk][0] = *(const float4*)(wr);
                bl[kk][1] = *(const float4*)(wr + 4);
            }
#pragma unroll
            for (int kk = 0; kk < 4; ++kk) {
                ull b[4];
                b[0] = pack2(bl[kk][0].x, bl[kk][0].y);
                b[1] = pack2(bl[kk][0].z, bl[kk][0].w);
                b[2] = pack2(bl[kk][1].x, bl[kk][1].y);
                b[3] = pack2(bl[kk][1].z, bl[kk][1].w);
#pragma unroll
                for (int i = 0; i < 8; i++) {
                    float av = (kk == 0) ? a[i].x : (kk == 1) ? a[i].y : (kk == 2) ? a[i].z : a[i].w;
                    ull ad = pack2(av, av);
#pragma unroll
                    for (int j = 0; j < 4; j++) acc.v[i][j] = ffma2(ad, b[j], acc.v[i][j]);
                }
            }
        }
    }
}

__device__ __forceinline__ void store_tile(const AccRM& acc, float* __restrict__ Y, int rb, int r0, int c0,
                                           const float* __restrict__ bias, bool do_act, int M) {
    float bb[8];
    if (bias) {
        float4 b0 = *(const float4*)(bias + c0);
        float4 b1 = *(const float4*)(bias + c0 + 4);
        bb[0] = b0.x; bb[1] = b0.y; bb[2] = b0.z; bb[3] = b0.w;
        bb[4] = b1.x; bb[5] = b1.y; bb[6] = b1.z; bb[7] = b1.w;
    } else {
#pragma unroll
        for (int j = 0; j < 8; j++) bb[j] = 0.f;
    }
#pragma unroll
    for (int i = 0; i < 8; i++) {
        int r = rb + r0 + i;
        if (r >= M) continue;
        float z[8];
        acc_row(acc, i, z);
#pragma unroll
        for (int j = 0; j < 8; j++) { z[j] += bb[j]; if (do_act) z[j] = lrelu(z[j]); }
        *(float4*)(Y + (size_t)r * DD + c0) = make_float4(z[0], z[1], z[2], z[3]);
        *(float4*)(Y + (size_t)r * DD + c0 + 4) = make_float4(z[4], z[5], z[6], z[7]);
    }
}

// ---------------- kernels ----------------
__global__ void k_zero() {
    int idx = blockIdx.x * blockDim.x + threadIdx.x;
    int stride = gridDim.x * blockDim.x;
    float4 z = make_float4(0.f, 0.f, 0.f, 0.f);
    for (int i = idx; i < NN * DD / 4; i += stride) ((float4*)g_hf)[i] = z;
    for (int i = idx; i < NN; i += stride) g_deg[i] = 0.f;
}

// W[K=128][N=128] fp32 -> [N][K] bf16 pairs, swizzled word layout, hi/lo
__global__ void k_wprep(const float* __restrict__ We, const float* __restrict__ Weu) {
    const float* W = (blockIdx.x == 0) ? We : (Weu + (size_t)256 * DD);
    uint32_t* oh = (blockIdx.x == 0) ? g_We_h : g_Wu_h;
    uint32_t* ol = (blockIdx.x == 0) ? g_We_l : g_Wu_l;
    for (int idx = threadIdx.x; idx < 128 * 64; idx += 256) {
        int n = idx >> 6;
        int wc = idx & 63;
        int k = wc * 2;
        float a = W[(size_t)k * DD + n];
        float b = W[(size_t)(k + 1) * DD + n];
        uint32_t hi, lo;
        split2(a, b, hi, lo);
        uint32_t w = aswz(n, wc);
        oh[w] = hi;
        ol[w] = lo;
    }
}

// Y = act(X @ W + b)
__global__ void __launch_bounds__(NTHR, 2) k_gemm_act(const float* __restrict__ X,
                                                      const float* __restrict__ W,
                                                      const float* __restrict__ bias,
                                                      float* __restrict__ Y, int M) {
    extern __shared__ float sm[];
    float* F = sm;
    float* Wsm = sm + DD * RSR;
    int tid = threadIdx.x, tx = tid & 15, ty = tid >> 4;
    int r0 = ty * 8, c0 = tx * 8;
    int rb = blockIdx.x * TILE_R;
    load_tile_rm<false>(X, rb, M, F, nullptr);
    AccRM acc; acc_zero(acc);
    mm_rm(F, W, Wsm, acc, r0, c0);
    store_tile(acc, Y, rb, r0, c0, bias, true, M);
}

__global__ void __launch_bounds__(NTHR, 2) k_nodepre(const float* __restrict__ Weu,
                                                     const float* __restrict__ beu,
                                                     const float* __restrict__ Wnu,
                                                     const float* __restrict__ bnu) {
    extern __shared__ float sm[];
    float* F = sm;
    float* Wsm = sm + DD * RSR;
    int tid = threadIdx.x, tx = tid & 15, ty = tid >> 4;
    int r0 = ty * 8, c0 = tx * 8;
    int rb = blockIdx.x * TILE_R;
    AccRM acc;

    load_tile_rm<false>(g_h, rb, NN, F, nullptr);
    acc_zero(acc);
    mm_rm(F, Weu, Wsm, acc, r0, c0);
    store_tile(acc, g_A, rb, r0, c0, nullptr, false, NN);

    acc_zero(acc);
    mm_rm(F, Weu + (size_t)128 * DD, Wsm, acc, r0, c0);
    __syncthreads();
    load_tile_rm<false>(g_u, rb, NN, F, nullptr);
    mm_rm(F, Weu + (size_t)384 * DD, Wsm, acc, r0, c0);
    store_tile(acc, g_Bm, rb, r0, c0, beu, false, NN);

    acc_zero(acc);
    mm_rm(F, Wnu + (size_t)256 * DD, Wsm, acc, r0, c0);
    __syncthreads();
    load_tile_rm<false>(g_h, rb, NN, F, nullptr);
    mm_rm(F, Wnu, Wsm, acc, r0, c0);
    store_tile(acc, g_C, rb, r0, c0, bnu, false, NN);
}

// ---------- persistent HMMA edge kernel ----------
// smem layout (bytes)
#define S_AH   0
#define S_AL   32768
#define S_W1H  65536
#define S_W1L  98304
#define S_W2H  131072
#define S_W2L  163840
#define S_SRC  196608
#define S_DST  197120
#define S_BE   197632
#define SMEM_EDGE (197632 + 512)

// acc: float[2][8][4] per warp (rows mr+32, cols nc+64)
__device__ __forceinline__ void gemm_mma(const uint32_t* __restrict__ Ah, const uint32_t* __restrict__ Al,
                                         const uint32_t* __restrict__ Wh, const uint32_t* __restrict__ Wl,
                                         float acc[2][8][4], int mr, int nc, int lane) {
#pragma unroll
    for (int mi = 0; mi < 2; mi++)
#pragma unroll
        for (int ni = 0; ni < 8; ni++)
#pragma unroll
            for (int q = 0; q < 4; q++) acc[mi][ni][q] = 0.f;

#pragma unroll 1
    for (int kb = 0; kb < 128; kb += 16) {
        int wc = (kb >> 1) + (lane & 3);
        uint32_t ah[2][4], al[2][4];
#pragma unroll
        for (int mi = 0; mi < 2; mi++) {
            int r0 = mr + mi * 16 + (lane >> 2);
            ah[mi][0] = Ah[aswz(r0, wc)];
            ah[mi][1] = Ah[aswz(r0 + 8, wc)];
            ah[mi][2] = Ah[aswz(r0, wc + 4)];
            ah[mi][3] = Ah[aswz(r0 + 8, wc + 4)];
            al[mi][0] = Al[aswz(r0, wc)];
            al[mi][1] = Al[aswz(r0 + 8, wc)];
            al[mi][2] = Al[aswz(r0, wc + 4)];
            al[mi][3] = Al[aswz(r0 + 8, wc + 4)];
        }
#pragma unroll
        for (int ni = 0; ni < 8; ni++) {
            int n0 = nc + ni * 8 + (lane >> 2);
            uint32_t b0h = Wh[aswz(n0, wc)];
            uint32_t b1h = Wh[aswz(n0, wc + 4)];
            uint32_t b0l = Wl[aswz(n0, wc)];
            uint32_t b1l = Wl[aswz(n0, wc + 4)];
#pragma unroll
            for (int mi = 0; mi < 2; mi++) {
                mma_bf16(acc[mi][ni], ah[mi][0], ah[mi][1], ah[mi][2], ah[mi][3], b0h, b1h);
                mma_bf16(acc[mi][ni], ah[mi][0], ah[mi][1], ah[mi][2], ah[mi][3], b0l, b1l);
                mma_bf16(acc[mi][ni], al[mi][0], al[mi][1], al[mi][2], al[mi][3], b0h, b1h);
            }
        }
    }
}

__global__ void __launch_bounds__(256, 1) k_edge_mma(const float* __restrict__ ef,
                                                     const int* __restrict__ src,
                                                     const int* __restrict__ dst,
                                                     const float* __restrict__ be,
                                                     float* __restrict__ out_edge) {
    extern __shared__ __align__(16) char smem[];
    uint32_t* Ah = (uint32_t*)(smem + S_AH);
    uint32_t* Al = (uint32_t*)(smem + S_AL);
    uint32_t* W1h = (uint32_t*)(smem + S_W1H);
    uint32_t* W1l = (uint32_t*)(smem + S_W1L);
    uint32_t* W2h = (uint32_t*)(smem + S_W2H);
    uint32_t* W2l = (uint32_t*)(smem + S_W2L);
    int* ssrc = (int*)(smem + S_SRC);
    int* sdst = (int*)(smem + S_DST);
    float* bes = (float*)(smem + S_BE);

    int tid = threadIdx.x, wid = tid >> 5, lane = tid & 31;
    int mr = (wid & 3) * 32, nc = (wid >> 2) * 64;

    // stage weights + bias once per CTA
    {
        uint4* d1 = (uint4*)W1h;
        uint4* d2 = (uint4*)W1l;
        uint4* d3 = (uint4*)W2h;
        uint4* d4 = (uint4*)W2l;
#pragma unroll
        for (int i = 0; i < 8; i++) {
            int j = i * 256 + tid;
            d1[j] = ((const uint4*)g_We_h)[j];
            d2[j] = ((const uint4*)g_We_l)[j];
            d3[j] = ((const uint4*)g_Wu_h)[j];
            d4[j] = ((const uint4*)g_Wu_l)[j];
        }
        if (tid < 128) bes[tid] = be[tid];
    }

    float acc[2][8][4];

    for (int t = blockIdx.x; t < EE / 128; t += gridDim.x) {
        int eb = t * 128;
        // stage A tile (ef) as bf16 hi/lo, swizzled
#pragma unroll
        for (int i = 0; i < 16; i++) {
            int idx = i * 256 + tid;
            int r = idx >> 5;
            int c4 = (idx & 31) * 4;
            float4 v = *(const float4*)(ef + (size_t)(eb + r) * DD + c4);
            uint32_t h0, l0, h1, l1;
            split2(v.x, v.y, h0, l0);
            split2(v.z, v.w, h1, l1);
            uint32_t w0 = aswz(r, c4 >> 1);
            Ah[w0] = h0; Ah[w0 + 1] = h1;
            Al[w0] = l0; Al[w0 + 1] = l1;
        }
        if (tid < 128) {
            ssrc[tid] = src[eb + tid];
            sdst[tid] = dst[eb + tid];
        }
        __syncthreads();

        // GEMM1: D1 = ef @ We
        gemm_mma(Ah, Al, W1h, W1l, acc, mr, nc, lane);
        __syncthreads();   // all A reads done before overwrite

        // epilogue1: f = lrelu(D1 + be) -> back into Ah/Al
#pragma unroll
        for (int mi = 0; mi < 2; mi++) {
            int R0 = mr + mi * 16 + (lane >> 2);
#pragma unroll
            for (int ni = 0; ni < 8; ni++) {
                int C = nc + ni * 8 + (lane & 3) * 2;
                float z0 = lrelu(acc[mi][ni][0] + bes[C]);
                float z1 = lrelu(acc[mi][ni][1] + bes[C + 1]);
                uint32_t h, l;
                split2(z0, z1, h, l);
                uint32_t w = aswz(R0, C >> 1);
                Ah[w] = h; Al[w] = l;
                z0 = lrelu(acc[mi][ni][2] + bes[C]);
                z1 = lrelu(acc[mi][ni][3] + bes[C + 1]);
                split2(z0, z1, h, l);
                w = aswz(R0 + 8, C >> 1);
                Ah[w] = h; Al[w] = l;
            }
        }
        __syncthreads();

        // GEMM2: D2 = f @ Weu2
        gemm_mma(Ah, Al, W2h, W2l, acc, mr, nc, lane);

        // epilogue2: f_new = lrelu(D2 + A[src] + Bm[dst]); outputs + segment sums
#pragma unroll
        for (int mi = 0; mi < 2; mi++) {
#pragma unroll
            for (int hh = 0; hh < 2; hh++) {
                int R = mr + mi * 16 + (lane >> 2) + hh * 8;
                int e = eb + R;
                int s = ssrc[R], d = sdst[R];
                int q0 = hh * 2;  // acc regs {0,1} or {2,3}
#pragma unroll
                for (int ni = 0; ni < 8; ni++) {
                    int C = nc + ni * 8 + (lane & 3) * 2;
                    float2 av = *(const float2*)(g_A + (size_t)s * DD + C);
                    float2 bv = *(const float2*)(g_Bm + (size_t)d * DD + C);
                    float2 ev = *(const float2*)(ef + (size_t)e * DD + C);
                    float f0 = lrelu(acc[mi][ni][q0] + av.x + bv.x);
                    float f1 = lrelu(acc[mi][ni][q0 + 1] + av.y + bv.y);
                    *(float2*)(out_edge + (size_t)e * DD + C) = make_float2(f0 + ev.x, f1 + ev.y);
                    atomicAdd((float2*)(g_hf + (size_t)d * DD + C), make_float2(f0, f1));
                }
                if (nc == 0 && (lane & 3) == 0) atomicAdd(&g_deg[d], 1.0f);
            }
        }
        __syncthreads();   // protect A/src/dst before next tile staging
    }
}

// node_new = act(C + (hf/max(deg,1)) @ Wnu1); out_node = node_new + node_feats
__global__ void __launch_bounds__(NTHR, 2) k_nodeupd(const float* __restrict__ Wnu,
                                                     const float* __restrict__ nf,
                                                     float* __restrict__ out_node) {
    extern __shared__ float sm[];
    float* F = sm;
    float* Wsm = sm + DD * RSR;
    float* sdeg = Wsm + WROWS * DD;
    int tid = threadIdx.x, tx = tid & 15, ty = tid >> 4;
    int r0 = ty * 8, c0 = tx * 8;
    int rb = blockIdx.x * TILE_R;
    if (tid < TILE_R) {
        int n = rb + tid;
        float dv = (n < NN) ? g_deg[n] : 1.f;
        sdeg[tid] = 1.f / fmaxf(dv, 1.f);
    }
    __syncthreads();
    load_tile_rm<true>(g_hf, rb, NN, F, sdeg);
    AccRM acc; acc_zero(acc);
    mm_rm(F, Wnu + (size_t)128 * DD, Wsm, acc, r0, c0);
#pragma unroll
    for (int i = 0; i < 8; i++) {
        int r = rb + r0 + i;
        if (r >= NN) continue;
        float z[8];
        acc_row(acc, i, z);
        const float4* pc = (const float4*)(g_C + (size_t)r * DD + c0);
        const float4* pn = (const float4*)(nf + (size_t)r * DD + c0);
        float4 c0v = pc[0], c1v = pc[1];
        float4 n0v = pn[0], n1v = pn[1];
        float nnv[8];
        nnv[0] = lrelu(z[0] + c0v.x); nnv[1] = lrelu(z[1] + c0v.y);
        nnv[2] = lrelu(z[2] + c0v.z); nnv[3] = lrelu(z[3] + c0v.w);
        nnv[4] = lrelu(z[4] + c1v.x); nnv[5] = lrelu(z[5] + c1v.y);
        nnv[6] = lrelu(z[6] + c1v.z); nnv[7] = lrelu(z[7] + c1v.w);
        *(float4*)(g_nn + (size_t)r * DD + c0) = make_float4(nnv[0], nnv[1], nnv[2], nnv[3]);
        *(float4*)(g_nn + (size_t)r * DD + c0 + 4) = make_float4(nnv[4], nnv[5], nnv[6], nnv[7]);
        *(float4*)(out_node + (size_t)r * DD + c0) =
            make_float4(nnv[0] + n0v.x, nnv[1] + n0v.y, nnv[2] + n0v.z, nnv[3] + n0v.w);
        *(float4*)(out_node + (size_t)r * DD + c0 + 4) =
            make_float4(nnv[4] + n1v.x, nnv[5] + n1v.y, nnv[6] + n1v.z, nnv[7] + n1v.w);
    }
}

__global__ void k_pool(const int* __restrict__ n2g, const float* __restrict__ gf,
                       const float* __restrict__ Wnu, const float* __restrict__ bnu) {
    int g = blockIdx.x;
    int c = threadIdx.x;
    int lo = 0, hi = NN;
    while (lo < hi) { int m = (lo + hi) >> 1; if (n2g[m] < g) lo = m + 1; else hi = m; }
    int s = lo;
    lo = s; hi = NN;
    while (lo < hi) { int m = (lo + hi) >> 1; if (n2g[m] < g + 1) lo = m + 1; else hi = m; }
    int e = lo;

    float sn = 0.f, se = 0.f, sg = 0.f;
    for (int n = s; n < e; ++n) {
        sn += g_nn[(size_t)n * DD + c];
        se += g_hf[(size_t)n * DD + c];
        sg += gf[(size_t)n * DD + c];
    }
    __shared__ float red[DD];
    float dls = 0.f;
    for (int n = s + c; n < e; n += DD) dls += g_deg[n];
    red[c] = dls;
    __syncthreads();
    for (int st = DD / 2; st > 0; st >>= 1) {
        if (c < st) red[c] += red[c + st];
        __syncthreads();
    }
    float degsum = red[0];
    float cnt = fmaxf((float)(e - s), 1.f);
    __shared__ float snp[DD], sep[DD], sgp[DD];
    snp[c] = sn / cnt;
    sep[c] = se / fmaxf(degsum, 1.f);
    sgp[c] = sg / cnt;
    __syncthreads();
    float z = bnu[c];
    for (int k = 0; k < DD; k++) {
        z += snp[k] * Wnu[(size_t)k * DD + c];
        z += sep[k] * Wnu[(size_t)(DD + k) * DD + c];
        z += sgp[k] * Wnu[(size_t)(2 * DD + k) * DD + c];
    }
    g_gnew[(size_t)g * DD + c] = lrelu(z);
}

__global__ void k_gout(const int* __restrict__ n2g, const float* __restrict__ gf,
                       float* __restrict__ out_graph) {
    int idx = blockIdx.x * blockDim.x + threadIdx.x;
    if (idx >= NN * (DD / 4)) return;
    int n = idx >> 5;
    int c4 = idx & 31;
    int g = n2g[n];
    float4 a = *(const float4*)(g_gnew + (size_t)g * DD + c4 * 4);
    float4 b = *(const float4*)(gf + (size_t)n * DD + c4 * 4);
    *(float4*)(out_graph + (size_t)n * DD + c4 * 4) = make_float4(a.x + b.x, a.y + b.y, a.z + b.z, a.w + b.w);
}

// ---------------- launch ----------------
extern "C" void kernel_launch(void* const* d_in, const int* in_sizes, int n_in,
                              void* d_out, int out_size) {
    const float* node_feats  = (const float*)d_in[0];
    const float* edge_feats  = (const float*)d_in[1];
    const float* graph_feats = (const float*)d_in[2];
    const int*   src = (const int*)d_in[3];
    const int*   dst = (const int*)d_in[4];
    const int*   n2g = (const int*)d_in[5];
    const float* Wn  = (const float*)d_in[6];
    const float* bn  = (const float*)d_in[7];
    const float* We  = (const float*)d_in[8];
    const float* be  = (const float*)d_in[9];
    const float* Wg  = (const float*)d_in[10];
    const float* bg  = (const float*)d_in[11];
    const float* Weu = (const float*)d_in[12];
    const float* beu = (const float*)d_in[13];
    const float* Wnu = (const float*)d_in[14];
    const float* bnu = (const float*)d_in[15];

    float* out_node  = (float*)d_out;
    float* out_edge  = out_node + (size_t)NN * DD;
    float* out_graph = out_edge + (size_t)EE * DD;

    const int base = (DD * RSR + WROWS * DD) * (int)sizeof(float);
    const int smem_g1  = base;
    const int smem_pre = base;
    const int smem_upd = base + TILE_R * (int)sizeof(float);

    cudaFuncSetAttribute(k_gemm_act, cudaFuncAttributeMaxDynamicSharedMemorySize, smem_g1);
    cudaFuncSetAttribute(k_nodepre,  cudaFuncAttributeMaxDynamicSharedMemorySize, smem_pre);
    cudaFuncSetAttribute(k_edge_mma, cudaFuncAttributeMaxDynamicSharedMemorySize, SMEM_EDGE);
    cudaFuncSetAttribute(k_nodeupd,  cudaFuncAttributeMaxDynamicSharedMemorySize, smem_upd);

    int nodeBlocks = (NN + TILE_R - 1) / TILE_R;  // 391

    float* d_gh; cudaGetSymbolAddress((void**)&d_gh, g_h);
    float* d_gu; cudaGetSymbolAddress((void**)&d_gu, g_u);

    k_zero<<<1024, NTHR>>>();
    k_wprep<<<2, 256>>>(We, Weu);
    k_gemm_act<<<nodeBlocks, NTHR, smem_g1>>>(node_feats, Wn, bn, d_gh, NN);
    k_gemm_act<<<nodeBlocks, NTHR, smem_g1>>>(graph_feats, Wg, bg, d_gu, NN);
    k_nodepre<<<nodeBlocks, NTHR, smem_pre>>>(Weu, beu, Wnu, bnu);
    k_edge_mma<<<304, 256, SMEM_EDGE>>>(edge_feats, src, dst, be, out_edge);
    k_nodeupd<<<nodeBlocks, NTHR, smem_upd>>>(Wnu, node_feats, out_node);
    k_pool<<<BB, DD>>>(n2g, graph_feats, Wnu, bnu);
    k_gout<<<(NN * (DD / 4) + NTHR - 1) / NTHR, NTHR>>>(n2g, graph_feats, out_graph);
}

// round 9
// speedup vs baseline: 2.2093x; 1.1627x over previous
#include <cuda_runtime.h>
#include <cuda_bf16.h>
#include <cstdint>

#define NN 50000
#define EE 800000
#define DD 128
#define BB 100
#define SLOPEV 0.01f

typedef unsigned long long ull;

// ---------------- scratch ----------------
__device__ float g_A[NN * DD];    // h @ Weu[0:128]
__device__ float g_Bm[NN * DD];   // h @ Weu[128:256] + u @ Weu[384:512] + beu
__device__ float g_C[NN * DD];    // h @ Wnu[0:128] + u @ Wnu[256:384] + bnu
__device__ float g_hf[NN * DD];
__device__ float g_deg[NN];
__device__ float g_nn[NN * DD];
__device__ float g_gnew[BB * DD];
// prepped B operands: 10 matrices, [N=128][K=128] bf16 pairs, XOR-swizzled, hi/lo
// idx: 0=Wn 1=Wg 2=We 3=Weu0 4=Weu1 5=Weu2 6=Weu3 7=Wnu0 8=Wnu1 9=Wnu2
__device__ uint32_t g_Wp_h[10 * 8192];
__device__ uint32_t g_Wp_l[10 * 8192];

// ---------------- helpers ----------------
__device__ __forceinline__ float lrelu(float x) { return x > 0.f ? x : SLOPEV * x; }
__device__ __forceinline__ void split2(float a, float b, uint32_t& hi, uint32_t& lo) {
    __nv_bfloat162 h = __floats2bfloat162_rn(a, b);
    float ra = a - __bfloat162float(h.x);
    float rb = b - __bfloat162float(h.y);
    __nv_bfloat162 l = __floats2bfloat162_rn(ra, rb);
    hi = *(uint32_t*)&h;
    lo = *(uint32_t*)&l;
}
// XOR-swizzled word index for a [128 rows][64 words] bf16-pair tile
__device__ __forceinline__ uint32_t aswz(int r, int wc) {
    return (uint32_t)(r * 64 + (wc ^ ((r & 7) << 2)));
}
__device__ __forceinline__ void mma_bf16(float* c, uint32_t a0, uint32_t a1, uint32_t a2, uint32_t a3,
                                         uint32_t b0, uint32_t b1) {
    asm volatile(
        "mma.sync.aligned.m16n8k16.row.col.f32.bf16.bf16.f32 "
        "{%0,%1,%2,%3}, {%4,%5,%6,%7}, {%8,%9}, {%0,%1,%2,%3};"
        : "+f"(c[0]), "+f"(c[1]), "+f"(c[2]), "+f"(c[3])
        : "r"(a0), "r"(a1), "r"(a2), "r"(a3), "r"(b0), "r"(b1));
}

// acc (+)= A(128x128) @ W^T ; per-warp patch rows [mr,mr+32) cols [nc,nc+64)
template <bool ACCUM>
__device__ __forceinline__ void gemm_mma(const uint32_t* __restrict__ Ah, const uint32_t* __restrict__ Al,
                                         const uint32_t* __restrict__ Wh, const uint32_t* __restrict__ Wl,
                                         float acc[2][8][4], int mr, int nc, int lane) {
    if (!ACCUM) {
#pragma unroll
        for (int mi = 0; mi < 2; mi++)
#pragma unroll
            for (int ni = 0; ni < 8; ni++)
#pragma unroll
                for (int q = 0; q < 4; q++) acc[mi][ni][q] = 0.f;
    }
#pragma unroll 1
    for (int kb = 0; kb < 128; kb += 16) {
        int wc = (kb >> 1) + (lane & 3);
        uint32_t ah[2][4], al[2][4];
#pragma unroll
        for (int mi = 0; mi < 2; mi++) {
            int r0 = mr + mi * 16 + (lane >> 2);
            ah[mi][0] = Ah[aswz(r0, wc)];
            ah[mi][1] = Ah[aswz(r0 + 8, wc)];
            ah[mi][2] = Ah[aswz(r0, wc + 4)];
            ah[mi][3] = Ah[aswz(r0 + 8, wc + 4)];
            al[mi][0] = Al[aswz(r0, wc)];
            al[mi][1] = Al[aswz(r0 + 8, wc)];
            al[mi][2] = Al[aswz(r0, wc + 4)];
            al[mi][3] = Al[aswz(r0 + 8, wc + 4)];
        }
#pragma unroll
        for (int ni = 0; ni < 8; ni++) {
            int n0 = nc + ni * 8 + (lane >> 2);
            uint32_t b0h = Wh[aswz(n0, wc)];
            uint32_t b1h = Wh[aswz(n0, wc + 4)];
            uint32_t b0l = Wl[aswz(n0, wc)];
            uint32_t b1l = Wl[aswz(n0, wc + 4)];
#pragma unroll
            for (int mi = 0; mi < 2; mi++) {
                mma_bf16(acc[mi][ni], ah[mi][0], ah[mi][1], ah[mi][2], ah[mi][3], b0h, b1h);
                mma_bf16(acc[mi][ni], ah[mi][0], ah[mi][1], ah[mi][2], ah[mi][3], b0l, b1l);
                mma_bf16(acc[mi][ni], al[mi][0], al[mi][1], al[mi][2], al[mi][3], b0h, b1h);
            }
        }
    }
}

// stage a [128 x 128] fp32 tile -> bf16 hi/lo swizzled smem; rows >= M zero-filled
template <bool SCALED>
__device__ __forceinline__ void stage_tile(const float* __restrict__ X, int rb, int M,
                                           uint32_t* __restrict__ Ah, uint32_t* __restrict__ Al,
                                           const float* __restrict__ rs, int tid) {
#pragma unroll
    for (int i = 0; i < 16; i++) {
        int idx = i * 256 + tid;
        int r = idx >> 5;
        int c4 = (idx & 31) * 4;
        float4 v = make_float4(0.f, 0.f, 0.f, 0.f);
        if (rb + r < M) v = *(const float4*)(X + (size_t)(rb + r) * DD + c4);
        if (SCALED) { float s = rs[r]; v.x *= s; v.y *= s; v.z *= s; v.w *= s; }
        uint32_t h0, l0, h1, l1;
        split2(v.x, v.y, h0, l0);
        split2(v.z, v.w, h1, l1);
        uint32_t w0 = aswz(r, c4 >> 1);
        Ah[w0] = h0; Ah[w0 + 1] = h1;
        Al[w0] = l0; Al[w0 + 1] = l1;
    }
}

// copy prepped weight idx into smem (8192 words each)
__device__ __forceinline__ void load_w(int idx, uint32_t* __restrict__ Wh, uint32_t* __restrict__ Wl, int tid) {
    const uint4* sh = (const uint4*)(g_Wp_h + idx * 8192);
    const uint4* sl = (const uint4*)(g_Wp_l + idx * 8192);
    uint4* dh = (uint4*)Wh;
    uint4* dl = (uint4*)Wl;
#pragma unroll
    for (int i = 0; i < 8; i++) {
        int j = i * 256 + tid;
        dh[j] = sh[j];
        dl[j] = sl[j];
    }
}

// epilogue helpers: fragment (R,C) mapping
// acc[mi][ni]: rows R0 = mr+mi*16+(lane>>2), R0+8 ; cols C = nc+ni*8+(lane&3)*2

// write act(acc + bias) back into Ah/Al (in-place f/h/u)
__device__ __forceinline__ void epi_to_smem(float acc[2][8][4], const float* __restrict__ bias,
                                            uint32_t* __restrict__ Ah, uint32_t* __restrict__ Al,
                                            int mr, int nc, int lane) {
#pragma unroll
    for (int mi = 0; mi < 2; mi++) {
        int R0 = mr + mi * 16 + (lane >> 2);
#pragma unroll
        for (int ni = 0; ni < 8; ni++) {
            int C = nc + ni * 8 + (lane & 3) * 2;
            float b0 = bias[C], b1 = bias[C + 1];
            float z0 = lrelu(acc[mi][ni][0] + b0);
            float z1 = lrelu(acc[mi][ni][1] + b1);
            uint32_t h, l;
            split2(z0, z1, h, l);
            uint32_t w = aswz(R0, C >> 1);
            Ah[w] = h; Al[w] = l;
            z0 = lrelu(acc[mi][ni][2] + b0);
            z1 = lrelu(acc[mi][ni][3] + b1);
            split2(z0, z1, h, l);
            w = aswz(R0 + 8, C >> 1);
            Ah[w] = h; Al[w] = l;
        }
    }
}

// write acc (+ optional bias) to global fp32 [M x DD]
__device__ __forceinline__ void epi_to_gmem(float acc[2][8][4], const float* __restrict__ bias,
                                            float* __restrict__ Y, int rb, int mr, int nc, int lane) {
#pragma unroll
    for (int mi = 0; mi < 2; mi++) {
#pragma unroll
        for (int hh = 0; hh < 2; hh++) {
            int R = mr + mi * 16 + (lane >> 2) + hh * 8;
            int r = rb + R;
            if (r >= NN) continue;
            int q0 = hh * 2;
#pragma unroll
            for (int ni = 0; ni < 8; ni++) {
                int C = nc + ni * 8 + (lane & 3) * 2;
                float b0 = bias ? bias[C] : 0.f;
                float b1 = bias ? bias[C + 1] : 0.f;
                *(float2*)(Y + (size_t)r * DD + C) =
                    make_float2(acc[mi][ni][q0] + b0, acc[mi][ni][q0 + 1] + b1);
            }
        }
    }
}

// ---------------- kernels ----------------
__global__ void k_zero() {
    int idx = blockIdx.x * blockDim.x + threadIdx.x;
    int stride = gridDim.x * blockDim.x;
    float4 z = make_float4(0.f, 0.f, 0.f, 0.f);
    for (int i = idx; i < NN * DD / 4; i += stride) ((float4*)g_hf)[i] = z;
    for (int i = idx; i < NN; i += stride) g_deg[i] = 0.f;
}

// W[K=128][N=128] fp32 -> [N][K] bf16 pairs, swizzled, hi/lo. grid=10
__global__ void k_wprep(const float* __restrict__ Wn, const float* __restrict__ Wg,
                        const float* __restrict__ We, const float* __restrict__ Weu,
                        const float* __restrict__ Wnu) {
    int b = blockIdx.x;
    const float* W;
    switch (b) {
        case 0: W = Wn; break;
        case 1: W = Wg; break;
        case 2: W = We; break;
        case 3: W = Weu; break;
        case 4: W = Weu + (size_t)128 * DD; break;
        case 5: W = Weu + (size_t)256 * DD; break;
        case 6: W = Weu + (size_t)384 * DD; break;
        case 7: W = Wnu; break;
        case 8: W = Wnu + (size_t)128 * DD; break;
        default: W = Wnu + (size_t)256 * DD; break;
    }
    uint32_t* oh = g_Wp_h + b * 8192;
    uint32_t* ol = g_Wp_l + b * 8192;
    for (int idx = threadIdx.x; idx < 128 * 64; idx += 256) {
        int n = idx >> 6;
        int wc = idx & 63;
        int k = wc * 2;
        float a = W[(size_t)k * DD + n];
        float c = W[(size_t)(k + 1) * DD + n];
        uint32_t hi, lo;
        split2(a, c, hi, lo);
        uint32_t w = aswz(n, wc);
        oh[w] = hi;
        ol[w] = lo;
    }
}

// ---------- fused node-pre kernel (HMMA) ----------
// h = act(nf@Wn+bn); u = act(gf@Wg+bg)  [smem only]
// A = h@Weu0 ; Bm = h@Weu1 + u@Weu3 + beu ; C = h@Wnu0 + u@Wnu2 + bnu
#define P_HH 0
#define P_HL 32768
#define P_UH 65536
#define P_UL 98304
#define P_WH 131072
#define P_WL 163840
#define P_B0 196608   // bn
#define P_B1 197120   // bg
#define P_B2 197632   // beu
#define P_B3 198144   // bnu
#define SMEM_PRE (198144 + 512)

__global__ void __launch_bounds__(256, 1) k_nodepre_mma(const float* __restrict__ nf,
                                                        const float* __restrict__ gf,
                                                        const float* __restrict__ bn,
                                                        const float* __restrict__ bg,
                                                        const float* __restrict__ beu,
                                                        const float* __restrict__ bnu) {
    extern __shared__ __align__(16) char smem[];
    uint32_t* Hh = (uint32_t*)(smem + P_HH);
    uint32_t* Hl = (uint32_t*)(smem + P_HL);
    uint32_t* Uh = (uint32_t*)(smem + P_UH);
    uint32_t* Ul = (uint32_t*)(smem + P_UL);
    uint32_t* Wh = (uint32_t*)(smem + P_WH);
    uint32_t* Wl = (uint32_t*)(smem + P_WL);
    float* b_n = (float*)(smem + P_B0);
    float* b_g = (float*)(smem + P_B1);
    float* b_eu = (float*)(smem + P_B2);
    float* b_nu = (float*)(smem + P_B3);

    int tid = threadIdx.x, wid = tid >> 5, lane = tid & 31;
    int mr = (wid & 3) * 32, nc = (wid >> 2) * 64;
    int rb = blockIdx.x * 128;

    if (tid < 128) {
        b_n[tid] = bn[tid];
        b_g[tid] = bg[tid];
        b_eu[tid] = beu[tid];
        b_nu[tid] = bnu[tid];
    }
    stage_tile<false>(nf, rb, NN, Hh, Hl, nullptr, tid);
    stage_tile<false>(gf, rb, NN, Uh, Ul, nullptr, tid);
    load_w(0, Wh, Wl, tid);   // Wn
    __syncthreads();

    float acc[2][8][4];

    // h = act(nf@Wn + bn)  (in place)
    gemm_mma<false>(Hh, Hl, Wh, Wl, acc, mr, nc, lane);
    __syncthreads();
    epi_to_smem(acc, b_n, Hh, Hl, mr, nc, lane);
    load_w(1, Wh, Wl, tid);   // Wg
    __syncthreads();

    // u = act(gf@Wg + bg)  (in place)
    gemm_mma<false>(Uh, Ul, Wh, Wl, acc, mr, nc, lane);
    __syncthreads();
    epi_to_smem(acc, b_g, Uh, Ul, mr, nc, lane);
    load_w(3, Wh, Wl, tid);   // Weu0
    __syncthreads();

    // A = h@Weu0
    gemm_mma<false>(Hh, Hl, Wh, Wl, acc, mr, nc, lane);
    __syncthreads();
    epi_to_gmem(acc, nullptr, g_A, rb, mr, nc, lane);
    load_w(4, Wh, Wl, tid);   // Weu1
    __syncthreads();

    // Bm = h@Weu1 + u@Weu3 + beu
    gemm_mma<false>(Hh, Hl, Wh, Wl, acc, mr, nc, lane);
    __syncthreads();
    load_w(6, Wh, Wl, tid);   // Weu3
    __syncthreads();
    gemm_mma<true>(Uh, Ul, Wh, Wl, acc, mr, nc, lane);
    __syncthreads();
    epi_to_gmem(acc, b_eu, g_Bm, rb, mr, nc, lane);
    load_w(7, Wh, Wl, tid);   // Wnu0
    __syncthreads();

    // C = h@Wnu0 + u@Wnu2 + bnu
    gemm_mma<false>(Hh, Hl, Wh, Wl, acc, mr, nc, lane);
    __syncthreads();
    load_w(9, Wh, Wl, tid);   // Wnu2
    __syncthreads();
    gemm_mma<true>(Uh, Ul, Wh, Wl, acc, mr, nc, lane);
    epi_to_gmem(acc, b_nu, g_C, rb, mr, nc, lane);
}

// ---------- persistent HMMA edge kernel (unchanged from R8) ----------
#define S_AH   0
#define S_AL   32768
#define S_W1H  65536
#define S_W1L  98304
#define S_W2H  131072
#define S_W2L  163840
#define S_SRC  196608
#define S_DST  197120
#define S_BE   197632
#define SMEM_EDGE (197632 + 512)

__global__ void __launch_bounds__(256, 1) k_edge_mma(const float* __restrict__ ef,
                                                     const int* __restrict__ src,
                                                     const int* __restrict__ dst,
                                                     const float* __restrict__ be,
                                                     float* __restrict__ out_edge) {
    extern __shared__ __align__(16) char smem[];
    uint32_t* Ah = (uint32_t*)(smem + S_AH);
    uint32_t* Al = (uint32_t*)(smem + S_AL);
    uint32_t* W1h = (uint32_t*)(smem + S_W1H);
    uint32_t* W1l = (uint32_t*)(smem + S_W1L);
    uint32_t* W2h = (uint32_t*)(smem + S_W2H);
    uint32_t* W2l = (uint32_t*)(smem + S_W2L);
    int* ssrc = (int*)(smem + S_SRC);
    int* sdst = (int*)(smem + S_DST);
    float* bes = (float*)(smem + S_BE);

    int tid = threadIdx.x, wid = tid >> 5, lane = tid & 31;
    int mr = (wid & 3) * 32, nc = (wid >> 2) * 64;

    load_w(2, W1h, W1l, tid);   // We
    load_w(5, W2h, W2l, tid);   // Weu2
    if (tid < 128) bes[tid] = be[tid];

    float acc[2][8][4];

    for (int t = blockIdx.x; t < EE / 128; t += gridDim.x) {
        int eb = t * 128;
        stage_tile<false>(ef, eb, EE, Ah, Al, nullptr, tid);
        if (tid < 128) {
            ssrc[tid] = src[eb + tid];
            sdst[tid] = dst[eb + tid];
        }
        __syncthreads();

        gemm_mma<false>(Ah, Al, W1h, W1l, acc, mr, nc, lane);
        __syncthreads();

        epi_to_smem(acc, bes, Ah, Al, mr, nc, lane);
        __syncthreads();

        gemm_mma<false>(Ah, Al, W2h, W2l, acc, mr, nc, lane);

#pragma unroll
        for (int mi = 0; mi < 2; mi++) {
#pragma unroll
            for (int hh = 0; hh < 2; hh++) {
                int R = mr + mi * 16 + (lane >> 2) + hh * 8;
                int e = eb + R;
                int s = ssrc[R], d = sdst[R];
                int q0 = hh * 2;
#pragma unroll
                for (int ni = 0; ni < 8; ni++) {
                    int C = nc + ni * 8 + (lane & 3) * 2;
                    float2 av = *(const float2*)(g_A + (size_t)s * DD + C);
                    float2 bv = *(const float2*)(g_Bm + (size_t)d * DD + C);
                    float2 ev = *(const float2*)(ef + (size_t)e * DD + C);
                    float f0 = lrelu(acc[mi][ni][q0] + av.x + bv.x);
                    float f1 = lrelu(acc[mi][ni][q0 + 1] + av.y + bv.y);
                    *(float2*)(out_edge + (size_t)e * DD + C) = make_float2(f0 + ev.x, f1 + ev.y);
                    atomicAdd((float2*)(g_hf + (size_t)d * DD + C), make_float2(f0, f1));
                }
                if (nc == 0 && (lane & 3) == 0) atomicAdd(&g_deg[d], 1.0f);
            }
        }
        __syncthreads();
    }
}

// ---------- node update (HMMA) ----------
// node_new = act(C + (hf/max(deg,1))@Wnu1); out_node = node_new + nf
#define U_AH 0
#define U_AL 32768
#define U_WH 65536
#define U_WL 98304
#define U_DG 131072
#define SMEM_UPD (131072 + 512)

__global__ void __launch_bounds__(256, 1) k_nodeupd_mma(const float* __restrict__ nf,
                                                        float* __restrict__ out_node) {
    extern __shared__ __align__(16) char smem[];
    uint32_t* Ah = (uint32_t*)(smem + U_AH);
    uint32_t* Al = (uint32_t*)(smem + U_AL);
    uint32_t* Wh = (uint32_t*)(smem + U_WH);
    uint32_t* Wl = (uint32_t*)(smem + U_WL);
    float* sdeg = (float*)(smem + U_DG);

    int tid = threadIdx.x, wid = tid >> 5, lane = tid & 31;
    int mr = (wid & 3) * 32, nc = (wid >> 2) * 64;
    int rb = blockIdx.x * 128;

    if (tid < 128) {
        int n = rb + tid;
        float dv = (n < NN) ? g_deg[n] : 1.f;
        sdeg[tid] = 1.f / fmaxf(dv, 1.f);
    }
    load_w(8, Wh, Wl, tid);   // Wnu1
    __syncthreads();
    stage_tile<true>(g_hf, rb, NN, Ah, Al, sdeg, tid);
    __syncthreads();

    float acc[2][8][4];
    gemm_mma<false>(Ah, Al, Wh, Wl, acc, mr, nc, lane);

#pragma unroll
    for (int mi = 0; mi < 2; mi++) {
#pragma unroll
        for (int hh = 0; hh < 2; hh++) {
            int R = mr + mi * 16 + (lane >> 2) + hh * 8;
            int r = rb + R;
            if (r >= NN) continue;
            int q0 = hh * 2;
#pragma unroll
            for (int ni = 0; ni < 8; ni++) {
                int C = nc + ni * 8 + (lane & 3) * 2;
                float2 cv = *(const float2*)(g_C + (size_t)r * DD + C);
                float2 nv = *(const float2*)(nf + (size_t)r * DD + C);
                float n0 = lrelu(acc[mi][ni][q0] + cv.x);
                float n1 = lrelu(acc[mi][ni][q0 + 1] + cv.y);
                *(float2*)(g_nn + (size_t)r * DD + C) = make_float2(n0, n1);
                *(float2*)(out_node + (size_t)r * DD + C) = make_float2(n0 + nv.x, n1 + nv.y);
            }
        }
    }
}

// ---------- pooling ----------
__global__ void k_pool(const int* __restrict__ n2g, const float* __restrict__ gf,
                       const float* __restrict__ Wnu, const float* __restrict__ bnu) {
    int g = blockIdx.x;
    int c = threadIdx.x;
    int lo = 0, hi = NN;
    while (lo < hi) { int m = (lo + hi) >> 1; if (n2g[m] < g) lo = m + 1; else hi = m; }
    int s = lo;
    lo = s; hi = NN;
    while (lo < hi) { int m = (lo + hi) >> 1; if (n2g[m] < g + 1) lo = m + 1; else hi = m; }
    int e = lo;

    float sn = 0.f, se = 0.f, sg = 0.f;
    for (int n = s; n < e; ++n) {
        sn += g_nn[(size_t)n * DD + c];
        se += g_hf[(size_t)n * DD + c];
        sg += gf[(size_t)n * DD + c];
    }
    __shared__ float red[DD];
    float dls = 0.f;
    for (int n = s + c; n < e; n += DD) dls += g_deg[n];
    red[c] = dls;
    __syncthreads();
    for (int st = DD / 2; st > 0; st >>= 1) {
        if (c < st) red[c] += red[c + st];
        __syncthreads();
    }
    float degsum = red[0];
    float cnt = fmaxf((float)(e - s), 1.f);
    __shared__ float snp[DD], sep[DD], sgp[DD];
    snp[c] = sn / cnt;
    sep[c] = se / fmaxf(degsum, 1.f);
    sgp[c] = sg / cnt;
    __syncthreads();
    float z = bnu[c];
    for (int k = 0; k < DD; k++) {
        z += snp[k] * Wnu[(size_t)k * DD + c];
        z += sep[k] * Wnu[(size_t)(DD + k) * DD + c];
        z += sgp[k] * Wnu[(size_t)(2 * DD + k) * DD + c];
    }
    g_gnew[(size_t)g * DD + c] = lrelu(z);
}

__global__ void k_gout(const int* __restrict__ n2g, const float* __restrict__ gf,
                       float* __restrict__ out_graph) {
    int idx = blockIdx.x * blockDim.x + threadIdx.x;
    if (idx >= NN * (DD / 4)) return;
    int n = idx >> 5;
    int c4 = idx & 31;
    int g = n2g[n];
    float4 a = *(const float4*)(g_gnew + (size_t)g * DD + c4 * 4);
    float4 b = *(const float4*)(gf + (size_t)n * DD + c4 * 4);
    *(float4*)(out_graph + (size_t)n * DD + c4 * 4) = make_float4(a.x + b.x, a.y + b.y, a.z + b.z, a.w + b.w);
}

// ---------------- launch ----------------
extern "C" void kernel_launch(void* const* d_in, const int* in_sizes, int n_in,
                              void* d_out, int out_size) {
    const float* node_feats  = (const float*)d_in[0];
    const float* edge_feats  = (const float*)d_in[1];
    const float* graph_feats = (const float*)d_in[2];
    const int*   src = (const int*)d_in[3];
    const int*   dst = (const int*)d_in[4];
    const int*   n2g = (const int*)d_in[5];
    const float* Wn  = (const float*)d_in[6];
    const float* bn  = (const float*)d_in[7];
    const float* We  = (const float*)d_in[8];
    const float* be  = (const float*)d_in[9];
    const float* Wg  = (const float*)d_in[10];
    const float* bg  = (const float*)d_in[11];
    const float* Weu = (const float*)d_in[12];
    const float* beu = (const float*)d_in[13];
    const float* Wnu = (const float*)d_in[14];
    const float* bnu = (const float*)d_in[15];

    float* out_node  = (float*)d_out;
    float* out_edge  = out_node + (size_t)NN * DD;
    float* out_graph = out_edge + (size_t)EE * DD;

    cudaFuncSetAttribute(k_nodepre_mma, cudaFuncAttributeMaxDynamicSharedMemorySize, SMEM_PRE);
    cudaFuncSetAttribute(k_edge_mma,    cudaFuncAttributeMaxDynamicSharedMemorySize, SMEM_EDGE);
    cudaFuncSetAttribute(k_nodeupd_mma, cudaFuncAttributeMaxDynamicSharedMemorySize, SMEM_UPD);

    int nodeBlocks = (NN + 127) / 128;  // 391

    k_zero<<<1024, 256>>>();
    k_wprep<<<10, 256>>>(Wn, Wg, We, Weu, Wnu);
    k_nodepre_mma<<<nodeBlocks, 256, SMEM_PRE>>>(node_feats, graph_feats, bn, bg, beu, bnu);
    k_edge_mma<<<304, 256, SMEM_EDGE>>>(edge_feats, src, dst, be, out_edge);
    k_nodeupd_mma<<<nodeBlocks, 256, SMEM_UPD>>>(node_feats, out_node);
    k_pool<<<BB, DD>>>(n2g, graph_feats, Wnu, bnu);
    k_gout<<<(NN * (DD / 4) + 255) / 256, 256>>>(n2g, graph_feats, out_graph);
}